// round 2
// baseline (speedup 1.0000x reference)
#include <cuda_runtime.h>
#include <cuda_bf16.h>
#include <math.h>

// Problem constants
#define Rr   16
#define Cc   256
#define Bb   12
#define Ee   768
#define Hh   12
#define Dd   64
#define RD   (Rr*Dd)          // 1024
#define NTOK (Rr*Cc*Bb)       // 49152
#define NB   32               // NUM_BUCKETS
#define SCALING 0.03125f      // D^-0.5 / sqrt(R) = 0.125/4

// Scratch (__device__ globals; no allocation allowed)
__device__ float g_q[(size_t)Bb*Hh*Cc*RD];     // (n,h,i,rd)   151MB
__device__ float g_k[(size_t)Bb*Hh*Cc*RD];     // (n,h,j,rd)
__device__ float g_v[(size_t)Bb*Hh*Cc*RD];     // (n,h,j,rd)
__device__ float g_s[(size_t)Hh*Bb*Cc*Cc];     // (h,n,i,j)    38MB
__device__ float g_ctx[(size_t)NTOK*Ee];       // (r,i,n, h*64+d) 151MB

// ---------------------------------------------------------------------------
// T5 relative-position bucket (distances are all >= 0 here)
// ---------------------------------------------------------------------------
__device__ __forceinline__ int rel_bucket(int dist) {
    if (dist < 16) return dist;
    float nf = fmaxf((float)dist, 1.0f);
    // matches: log(n/16) / np.log(50000/16) * 15, trunc toward zero
    float v = logf(nf * (1.0f/16.0f)) / 8.047189562170502f * 15.0f;
    int b = 16 + (int)v;
    return b < 31 ? b : 31;
}

// ---------------------------------------------------------------------------
// GEMM tile config: 128x128 block, BK=8, 256 threads, 8x8 per thread
// (two 4x4 quads at +0 / +64 in each dim for conflict-light smem reads)
// ---------------------------------------------------------------------------

// Kernel 1: fused Q/K/V projection + scatter.
// C[m][e] = sum_k x[m][k] * W[e][k] + bias[e]   (NT)
__global__ __launch_bounds__(256) void proj_qkv_kernel(
    const float* __restrict__ x,
    const float* __restrict__ Wq, const float* __restrict__ bq,
    const float* __restrict__ Wk, const float* __restrict__ bk,
    const float* __restrict__ Wv, const float* __restrict__ bv)
{
    __shared__ float As[8][128];
    __shared__ float Bs[8][128];

    const int z  = blockIdx.z;
    const float* W    = (z == 0) ? Wq : (z == 1) ? Wk : Wv;
    const float* bias = (z == 0) ? bq : (z == 1) ? bk : bv;
    float*       dst  = (z == 0) ? g_q : (z == 1) ? g_k : g_v;
    const float  scale = (z == 0) ? SCALING : 1.0f;

    const int m0 = blockIdx.y * 128;
    const int n0 = blockIdx.x * 128;
    const int tid = threadIdx.x;
    const int tx = tid & 15, ty = tid >> 4;
    const int lrow = tid >> 1, lcol = (tid & 1) * 4;

    float acc[8][8];
    #pragma unroll
    for (int i = 0; i < 8; i++)
        #pragma unroll
        for (int j = 0; j < 8; j++) acc[i][j] = 0.0f;

    const float* Ag = x + (size_t)(m0 + lrow) * Ee + lcol;
    const float* Bg = W + (size_t)(n0 + lrow) * Ee + lcol;

    for (int k0 = 0; k0 < Ee; k0 += 8) {
        float4 av = *(const float4*)(Ag + k0);
        float4 bv4 = *(const float4*)(Bg + k0);
        __syncthreads();
        As[lcol+0][lrow] = av.x;  As[lcol+1][lrow] = av.y;
        As[lcol+2][lrow] = av.z;  As[lcol+3][lrow] = av.w;
        Bs[lcol+0][lrow] = bv4.x; Bs[lcol+1][lrow] = bv4.y;
        Bs[lcol+2][lrow] = bv4.z; Bs[lcol+3][lrow] = bv4.w;
        __syncthreads();
        #pragma unroll
        for (int kk = 0; kk < 8; kk++) {
            float4 a0 = *(const float4*)&As[kk][ty*4];
            float4 a1 = *(const float4*)&As[kk][64 + ty*4];
            float4 b0 = *(const float4*)&Bs[kk][tx*4];
            float4 b1 = *(const float4*)&Bs[kk][64 + tx*4];
            float a[8] = {a0.x,a0.y,a0.z,a0.w,a1.x,a1.y,a1.z,a1.w};
            float b[8] = {b0.x,b0.y,b0.z,b0.w,b1.x,b1.y,b1.z,b1.w};
            #pragma unroll
            for (int i = 0; i < 8; i++)
                #pragma unroll
                for (int j = 0; j < 8; j++) acc[i][j] += a[i]*b[j];
        }
    }

    // Epilogue: scatter into (n, h, i, r*64+d), apply bias (+ scaling for q)
    #pragma unroll
    for (int ii = 0; ii < 8; ii++) {
        int mrel = (ii < 4) ? (ty*4 + ii) : (64 + ty*4 + ii - 4);
        int m = m0 + mrel;
        int r   = m / (Cc*Bb);
        int rem = m - r * (Cc*Bb);
        int ci  = rem / Bb;
        int n   = rem - ci * Bb;
        #pragma unroll
        for (int jj = 0; jj < 8; jj++) {
            int erel = (jj < 4) ? (tx*4 + jj) : (64 + tx*4 + jj - 4);
            int e = n0 + erel;
            int h = e >> 6, d = e & 63;
            float vv = (acc[ii][jj] + __ldg(&bias[e])) * scale;
            dst[(((size_t)n*Hh + h)*Cc + ci)*RD + r*Dd + d] = vv;
        }
    }
}

// Kernel 2: scores S[h,n,i,j] = Q_nh[i,:] . K_nh[j,:] + bias   (NT, K=1024)
__global__ __launch_bounds__(256) void scores_kernel(
    const int* __restrict__ distances, const float* __restrict__ rel_bias)
{
    __shared__ float As[8][128];
    __shared__ float Bs[8][128];

    const int z = blockIdx.z;           // z = h*Bb + n
    const int h = z / Bb, n = z % Bb;
    const size_t base = ((size_t)n*Hh + h) * Cc * RD;

    const int m0 = blockIdx.y * 128;
    const int n0 = blockIdx.x * 128;
    const int tid = threadIdx.x;
    const int tx = tid & 15, ty = tid >> 4;
    const int lrow = tid >> 1, lcol = (tid & 1) * 4;

    float acc[8][8];
    #pragma unroll
    for (int i = 0; i < 8; i++)
        #pragma unroll
        for (int j = 0; j < 8; j++) acc[i][j] = 0.0f;

    const float* Ag = g_q + base + (size_t)(m0 + lrow) * RD + lcol;
    const float* Bg = g_k + base + (size_t)(n0 + lrow) * RD + lcol;

    for (int k0 = 0; k0 < RD; k0 += 8) {
        float4 av = *(const float4*)(Ag + k0);
        float4 bv4 = *(const float4*)(Bg + k0);
        __syncthreads();
        As[lcol+0][lrow] = av.x;  As[lcol+1][lrow] = av.y;
        As[lcol+2][lrow] = av.z;  As[lcol+3][lrow] = av.w;
        Bs[lcol+0][lrow] = bv4.x; Bs[lcol+1][lrow] = bv4.y;
        Bs[lcol+2][lrow] = bv4.z; Bs[lcol+3][lrow] = bv4.w;
        __syncthreads();
        #pragma unroll
        for (int kk = 0; kk < 8; kk++) {
            float4 a0 = *(const float4*)&As[kk][ty*4];
            float4 a1 = *(const float4*)&As[kk][64 + ty*4];
            float4 b0 = *(const float4*)&Bs[kk][tx*4];
            float4 b1 = *(const float4*)&Bs[kk][64 + tx*4];
            float a[8] = {a0.x,a0.y,a0.z,a0.w,a1.x,a1.y,a1.z,a1.w};
            float b[8] = {b0.x,b0.y,b0.z,b0.w,b1.x,b1.y,b1.z,b1.w};
            #pragma unroll
            for (int i = 0; i < 8; i++)
                #pragma unroll
                for (int j = 0; j < 8; j++) acc[i][j] += a[i]*b[j];
        }
    }

    float* Sdst = g_s + (size_t)z * Cc * Cc;
    #pragma unroll
    for (int ii = 0; ii < 8; ii++) {
        int i = m0 + ((ii < 4) ? (ty*4 + ii) : (64 + ty*4 + ii - 4));
        #pragma unroll
        for (int jj = 0; jj < 8; jj++) {
            int j = n0 + ((jj < 4) ? (tx*4 + jj) : (64 + tx*4 + jj - 4));
            // positional add quirk (B==H): distances indexed by h, bias column by n
            int dist = __ldg(&distances[((size_t)h*Cc + i)*Cc + j]);
            int bu = rel_bucket(dist);
            float bias = __ldg(&rel_bias[bu*Hh + n]);
            Sdst[(size_t)i*Cc + j] = acc[ii][jj] + bias;
        }
    }
}

// Kernel 3: in-place row softmax over last dim (256) of g_s
__global__ __launch_bounds__(256) void softmax_kernel()
{
    float* p = g_s + (size_t)blockIdx.x * Cc;
    const int t = threadIdx.x;
    const int lane = t & 31, w = t >> 5;
    __shared__ float red[8];

    float v = p[t];

    float m = v;
    #pragma unroll
    for (int o = 16; o > 0; o >>= 1)
        m = fmaxf(m, __shfl_xor_sync(0xffffffffu, m, o));
    if (lane == 0) red[w] = m;
    __syncthreads();
    if (w == 0) {
        float mm = red[lane & 7];
        #pragma unroll
        for (int o = 4; o > 0; o >>= 1)
            mm = fmaxf(mm, __shfl_xor_sync(0xffffffffu, mm, o));
        if (lane == 0) red[0] = mm;
    }
    __syncthreads();
    m = red[0];
    __syncthreads();

    float e = expf(v - m);
    float s = e;
    #pragma unroll
    for (int o = 16; o > 0; o >>= 1)
        s += __shfl_xor_sync(0xffffffffu, s, o);
    if (lane == 0) red[w] = s;
    __syncthreads();
    if (w == 0) {
        float ss = red[lane & 7];
        #pragma unroll
        for (int o = 4; o > 0; o >>= 1)
            ss += __shfl_xor_sync(0xffffffffu, ss, o);
        if (lane == 0) red[0] = ss;
    }
    __syncthreads();
    float denom = red[0];

    p[t] = e / denom;
}

// Kernel 4: ctx_nh[i, rd] = sum_j P_nh[i,j] * V_nh[j, rd]   (NN, K=256)
__global__ __launch_bounds__(256) void ctx_kernel()
{
    __shared__ float As[8][128];
    __shared__ float Bs[8][128];

    const int z = blockIdx.z;           // z = h*Bb + n
    const int h = z / Bb, n = z % Bb;

    const int m0 = blockIdx.y * 128;    // i
    const int n0 = blockIdx.x * 128;    // rd
    const int tid = threadIdx.x;
    const int tx = tid & 15, ty = tid >> 4;
    const int lrow = tid >> 1, lcol = (tid & 1) * 4;     // A-tile (transposed store)
    const int bkrow = tid >> 5, bcol = (tid & 31) * 4;   // B-tile (direct store)

    float acc[8][8];
    #pragma unroll
    for (int i = 0; i < 8; i++)
        #pragma unroll
        for (int j = 0; j < 8; j++) acc[i][j] = 0.0f;

    const float* Ag = g_s + (size_t)z * Cc * Cc + (size_t)(m0 + lrow) * Cc + lcol;
    const float* Bg = g_v + ((size_t)n*Hh + h) * Cc * RD;   // (j, rd), ld = 1024

    for (int k0 = 0; k0 < Cc; k0 += 8) {
        float4 av = *(const float4*)(Ag + k0);
        float4 bv4 = *(const float4*)(Bg + (size_t)(k0 + bkrow) * RD + n0 + bcol);
        __syncthreads();
        As[lcol+0][lrow] = av.x; As[lcol+1][lrow] = av.y;
        As[lcol+2][lrow] = av.z; As[lcol+3][lrow] = av.w;
        *(float4*)&Bs[bkrow][bcol] = bv4;
        __syncthreads();
        #pragma unroll
        for (int kk = 0; kk < 8; kk++) {
            float4 a0 = *(const float4*)&As[kk][ty*4];
            float4 a1 = *(const float4*)&As[kk][64 + ty*4];
            float4 b0 = *(const float4*)&Bs[kk][tx*4];
            float4 b1 = *(const float4*)&Bs[kk][64 + tx*4];
            float a[8] = {a0.x,a0.y,a0.z,a0.w,a1.x,a1.y,a1.z,a1.w};
            float b[8] = {b0.x,b0.y,b0.z,b0.w,b1.x,b1.y,b1.z,b1.w};
            #pragma unroll
            for (int i = 0; i < 8; i++)
                #pragma unroll
                for (int j = 0; j < 8; j++) acc[i][j] += a[i]*b[j];
        }
    }

    // Scatter: ctx[r, i(ci), n, h*64+d]
    #pragma unroll
    for (int ii = 0; ii < 8; ii++) {
        int i = m0 + ((ii < 4) ? (ty*4 + ii) : (64 + ty*4 + ii - 4));
        #pragma unroll
        for (int jj = 0; jj < 8; jj++) {
            int rd = n0 + ((jj < 4) ? (tx*4 + jj) : (64 + tx*4 + jj - 4));
            int r = rd >> 6, d = rd & 63;
            g_ctx[(((size_t)r*Cc + i)*Bb + n)*Ee + h*Dd + d] = acc[ii][jj];
        }
    }
}

// Kernel 5: out[m][e] = sum_k ctx[m][k] * Wo[e][k] + bo[e]   (NT)
__global__ __launch_bounds__(256) void outproj_kernel(
    const float* __restrict__ Wo, const float* __restrict__ bo,
    float* __restrict__ out)
{
    __shared__ float As[8][128];
    __shared__ float Bs[8][128];

    const int m0 = blockIdx.y * 128;
    const int n0 = blockIdx.x * 128;
    const int tid = threadIdx.x;
    const int tx = tid & 15, ty = tid >> 4;
    const int lrow = tid >> 1, lcol = (tid & 1) * 4;

    float acc[8][8];
    #pragma unroll
    for (int i = 0; i < 8; i++)
        #pragma unroll
        for (int j = 0; j < 8; j++) acc[i][j] = 0.0f;

    const float* Ag = g_ctx + (size_t)(m0 + lrow) * Ee + lcol;
    const float* Bg = Wo    + (size_t)(n0 + lrow) * Ee + lcol;

    for (int k0 = 0; k0 < Ee; k0 += 8) {
        float4 av = *(const float4*)(Ag + k0);
        float4 bv4 = *(const float4*)(Bg + k0);
        __syncthreads();
        As[lcol+0][lrow] = av.x;  As[lcol+1][lrow] = av.y;
        As[lcol+2][lrow] = av.z;  As[lcol+3][lrow] = av.w;
        Bs[lcol+0][lrow] = bv4.x; Bs[lcol+1][lrow] = bv4.y;
        Bs[lcol+2][lrow] = bv4.z; Bs[lcol+3][lrow] = bv4.w;
        __syncthreads();
        #pragma unroll
        for (int kk = 0; kk < 8; kk++) {
            float4 a0 = *(const float4*)&As[kk][ty*4];
            float4 a1 = *(const float4*)&As[kk][64 + ty*4];
            float4 b0 = *(const float4*)&Bs[kk][tx*4];
            float4 b1 = *(const float4*)&Bs[kk][64 + tx*4];
            float a[8] = {a0.x,a0.y,a0.z,a0.w,a1.x,a1.y,a1.z,a1.w};
            float b[8] = {b0.x,b0.y,b0.z,b0.w,b1.x,b1.y,b1.z,b1.w};
            #pragma unroll
            for (int i = 0; i < 8; i++)
                #pragma unroll
                for (int j = 0; j < 8; j++) acc[i][j] += a[i]*b[j];
        }
    }

    #pragma unroll
    for (int ii = 0; ii < 8; ii++) {
        int m = m0 + ((ii < 4) ? (ty*4 + ii) : (64 + ty*4 + ii - 4));
        #pragma unroll
        for (int jj = 0; jj < 8; jj++) {
            int e = n0 + ((jj < 4) ? (tx*4 + jj) : (64 + tx*4 + jj - 4));
            out[(size_t)m*Ee + e] = acc[ii][jj] + __ldg(&bo[e]);
        }
    }
}

// Kernel 6: copy probs (g_s already in (h,n,i,j) layout) into d_out tail
__global__ __launch_bounds__(256) void copy_probs_kernel(float* __restrict__ dst)
{
    size_t idx = (size_t)blockIdx.x * 256 + threadIdx.x;
    ((float4*)dst)[idx] = ((const float4*)g_s)[idx];
}

// ---------------------------------------------------------------------------
extern "C" void kernel_launch(void* const* d_in, const int* in_sizes, int n_in,
                              void* d_out, int out_size)
{
    const float* x         = (const float*)d_in[0];
    const int*   distances = (const int*)  d_in[1];
    const float* Wq = (const float*)d_in[2];
    const float* bq = (const float*)d_in[3];
    const float* Wk = (const float*)d_in[4];
    const float* bk = (const float*)d_in[5];
    const float* Wv = (const float*)d_in[6];
    const float* bv = (const float*)d_in[7];
    const float* Wo = (const float*)d_in[8];
    const float* bo = (const float*)d_in[9];
    const float* rel_bias = (const float*)d_in[10];
    float* out = (float*)d_out;

    dim3 blk(256);

    // 1. Q/K/V projections (N=49152 x E=768, K=768), z selects q/k/v
    proj_qkv_kernel<<<dim3(Ee/128, NTOK/128, 3), blk>>>(x, Wq, bq, Wk, bk, Wv, bv);

    // 2. Scores: per (h,n) 256x256, K=1024 (+ bucket bias)
    scores_kernel<<<dim3(2, 2, Hh*Bb), blk>>>(distances, rel_bias);

    // 3. Softmax over rows of g_s
    softmax_kernel<<<Hh*Bb*Cc, 256>>>();

    // 4. Context: per (h,n) 256x1024, K=256
    ctx_kernel<<<dim3(RD/128, 2, Hh*Bb), blk>>>();

    // 5. Output projection -> d_out[0 .. NTOK*Ee)
    outproj_kernel<<<dim3(Ee/128, NTOK/128), blk>>>(Wo, bo, out);

    // 6. probs -> d_out tail (if the harness expects the (out, probs) tuple)
    const size_t out_elems   = (size_t)NTOK * Ee;            // 37,748,736
    const size_t probs_elems = (size_t)Hh * Bb * Cc * Cc;    //  9,437,184
    if ((size_t)out_size >= out_elems + probs_elems) {
        copy_probs_kernel<<<(unsigned)(probs_elems / 4 / 256), blk>>>(out + out_elems);
    }
}

// round 4
// speedup vs baseline: 2.8619x; 2.8619x over previous
#include <cuda_runtime.h>
#include <cuda_bf16.h>
#include <math.h>
#include <stdint.h>

#define Rr   16
#define Cc   256
#define Bb   12
#define Ee   768
#define Hh   12
#define Dd   64
#define RD   1024
#define NTOK 49152
#define SCALING 0.03125f

__device__ float g_q  [(size_t)NTOK*Ee];
__device__ float g_k  [(size_t)NTOK*Ee];
__device__ float g_v  [(size_t)NTOK*Ee];
__device__ float g_vt [(size_t)Hh*Bb*RD*Cc];
__device__ float g_s  [(size_t)Hh*Bb*Cc*Cc];
__device__ float g_ctx[(size_t)NTOK*Ee];
__device__ unsigned char g_buck[(size_t)Hh*Cc*Cc];

#define SMEM_DYN 65536   // 2 stages x (A 16KB + B 16KB)

// ---------------- helpers ----------------
__device__ __forceinline__ uint32_t smem_u32(const void* p) {
    uint32_t a;
    asm("{ .reg .u64 t; cvta.to.shared.u64 t, %1; cvt.u32.u64 %0, t; }" : "=r"(a) : "l"(p));
    return a;
}
__device__ __forceinline__ uint4 cvt4_tf32(float4 v) {
    uint4 u;
    asm("cvt.rna.tf32.f32 %0, %1;" : "=r"(u.x) : "f"(v.x));
    asm("cvt.rna.tf32.f32 %0, %1;" : "=r"(u.y) : "f"(v.y));
    asm("cvt.rna.tf32.f32 %0, %1;" : "=r"(u.z) : "f"(v.z));
    asm("cvt.rna.tf32.f32 %0, %1;" : "=r"(u.w) : "f"(v.w));
    return u;
}
__device__ __forceinline__ void sts128u(uint32_t a, uint4 u) {
    asm volatile("st.shared.v4.b32 [%0], {%1,%2,%3,%4};"
                 :: "r"(a), "r"(u.x), "r"(u.y), "r"(u.z), "r"(u.w) : "memory");
}
#define LDSM4(r, addr) \
    asm volatile("ldmatrix.sync.aligned.m8n8.x4.shared.b16 {%0,%1,%2,%3}, [%4];" \
        : "=r"((r)[0]), "=r"((r)[1]), "=r"((r)[2]), "=r"((r)[3]) : "r"(addr))
#define MMA_TF32(d, a, b) \
    asm volatile("mma.sync.aligned.m16n8k8.row.col.f32.tf32.tf32.f32 " \
        "{%0,%1,%2,%3}, {%4,%5,%6,%7}, {%8,%9}, {%0,%1,%2,%3};" \
        : "+f"((d)[0]), "+f"((d)[1]), "+f"((d)[2]), "+f"((d)[3]) \
        : "r"((a)[0]), "r"((a)[1]), "r"((a)[2]), "r"((a)[3]), \
          "r"((b)[0]), "r"((b)[1]))

// ---------------- shared GEMM core ----------------
// Block 128(M) x 128(N), K-chunk = 32 f32.  Both operands K-contiguous (NT).
// SMEM tile: 128 rows x 128B, 16B chunks XOR-swizzled: addr = row*128 + ((c16 ^ (row&7))<<4)
struct GP { const float4 *a[4], *b[4]; };

__device__ __forceinline__ void gemm_mma(const GP& P, int NC, long roff4, bool split,
                                         float acc[4][4][4])
{
    extern __shared__ uint32_t smem[];
    const uint32_t sbase = smem_u32(smem);
    const int t = threadIdx.x;
    const int lane = t & 31, wid = t >> 5;
    const int wm = wid >> 2, wn = wid & 3;

    uint32_t sts[4];
    {
        const int c16 = t & 7;
        #pragma unroll
        for (int i = 0; i < 4; i++) {
            int row = (t >> 3) + 32 * i;
            sts[i] = (uint32_t)(row * 128 + ((c16 ^ (row & 7)) << 4));
        }
    }
    #pragma unroll
    for (int mt = 0; mt < 4; mt++)
        #pragma unroll
        for (int nt = 0; nt < 4; nt++)
            #pragma unroll
            for (int r = 0; r < 4; r++) acc[mt][nt][r] = 0.0f;

    float4 ra[4], rb[4];
    // prologue: chunk 0 -> buffer 0
    {
        const long o = split ? 0 : 0;
        #pragma unroll
        for (int i = 0; i < 4; i++) { ra[i] = __ldg(P.a[i] + o); rb[i] = __ldg(P.b[i] + o); }
        #pragma unroll
        for (int i = 0; i < 4; i++) {
            sts128u(sbase + sts[i], cvt4_tf32(ra[i]));
            sts128u(sbase + 16384u + sts[i], cvt4_tf32(rb[i]));
        }
        __syncthreads();
    }

    for (int c = 0; c < NC; c++) {
        if (c + 1 < NC) {
            const int cn = c + 1;
            const long o = split ? ((long)(cn >> 1) * roff4 + (long)(cn & 1) * 8)
                                 : (long)cn * 8;
            #pragma unroll
            for (int i = 0; i < 4; i++) { ra[i] = __ldg(P.a[i] + o); rb[i] = __ldg(P.b[i] + o); }
        }
        const uint32_t sa = sbase + (uint32_t)(c & 1) * 32768u;
        const uint32_t sb = sa + 16384u;
        #pragma unroll
        for (int ks = 0; ks < 4; ks++) {
            uint32_t af[4][4], bf[4][2];
            #pragma unroll
            for (int mt = 0; mt < 4; mt++) {
                int row = wm * 64 + mt * 16 + (lane & 15);
                int c16 = ks * 2 + (lane >> 4);
                LDSM4(af[mt], sa + row * 128 + ((c16 ^ (row & 7)) << 4));
            }
            #pragma unroll
            for (int p = 0; p < 2; p++) {
                int mm = lane >> 3;
                int row = wn * 32 + p * 16 + ((mm >> 1) << 3) + (lane & 7);
                int c16 = ks * 2 + (mm & 1);
                uint32_t r4[4];
                LDSM4(r4, sb + row * 128 + ((c16 ^ (row & 7)) << 4));
                bf[2*p+0][0] = r4[0]; bf[2*p+0][1] = r4[1];
                bf[2*p+1][0] = r4[2]; bf[2*p+1][1] = r4[3];
            }
            #pragma unroll
            for (int mt = 0; mt < 4; mt++)
                #pragma unroll
                for (int nt = 0; nt < 4; nt++)
                    MMA_TF32(acc[mt][nt], af[mt], bf[nt]);
        }
        if (c + 1 < NC) {
            const uint32_t da = sbase + (uint32_t)((c + 1) & 1) * 32768u;
            #pragma unroll
            for (int i = 0; i < 4; i++) {
                sts128u(da + sts[i], cvt4_tf32(ra[i]));
                sts128u(da + 16384u + sts[i], cvt4_tf32(rb[i]));
            }
        }
        __syncthreads();
    }
}

// Epilogue index helpers (per warp/lane): row0 = m0 + wm*64 + lane/4 (+mt*16, +8)
//                                         col0 = n0 + wn*32 + (lane&3)*2 (+nt*8)
#define EPI_IDX()                                                         \
    const int lane = threadIdx.x & 31, wid = threadIdx.x >> 5;            \
    const int wm = wid >> 2, wn = wid & 3;                                \
    const int grow0 = m0 + wm * 64 + (lane >> 2);                         \
    const int gcol0 = n0 + wn * 32 + (lane & 3) * 2;

// ---------------- bucket precompute ----------------
__device__ __forceinline__ int rel_bucket(int dist) {
    if (dist < 16) return dist;
    float v = logf(fmaxf((float)dist, 1.0f) * 0.0625f) * (15.0f / 8.047189562170502f);
    int b = 16 + (int)v;
    return b < 31 ? b : 31;
}
__global__ __launch_bounds__(256) void bucketize_kernel(const int* __restrict__ dist) {
    size_t i = (size_t)blockIdx.x * 256 + threadIdx.x;
    g_buck[i] = (unsigned char)rel_bucket(__ldg(&dist[i]));
}

// ---------------- K1: QKV projection ----------------
__global__ __launch_bounds__(256) void proj_mma(
    const float* __restrict__ x,
    const float* __restrict__ Wq, const float* __restrict__ bq,
    const float* __restrict__ Wk, const float* __restrict__ bk,
    const float* __restrict__ Wv, const float* __restrict__ bv)
{
    const int w  = blockIdx.z;
    const int n0 = blockIdx.x * 128;
    const int m0 = blockIdx.y * 128;
    const float* W    = (w == 0) ? Wq : (w == 1) ? Wk : Wv;
    const float* bias = (w == 0) ? bq : (w == 1) ? bk : bv;
    float*       dst  = (w == 0) ? g_q : (w == 1) ? g_k : g_v;
    const float  scale = (w == 0) ? SCALING : 1.0f;

    GP P;
    {
        const int rl = threadIdx.x >> 3, c4 = threadIdx.x & 7;
        #pragma unroll
        for (int i = 0; i < 4; i++) {
            P.a[i] = (const float4*)(x + (size_t)(m0 + rl + 32*i) * Ee) + c4;
            P.b[i] = (const float4*)(W + (size_t)(n0 + rl + 32*i) * Ee) + c4;
        }
    }
    float acc[4][4][4];
    gemm_mma(P, 24, 0, false, acc);

    EPI_IDX();
    #pragma unroll
    for (int mt = 0; mt < 4; mt++) {
        const int rA = grow0 + mt * 16, rB = rA + 8;
        #pragma unroll
        for (int nt = 0; nt < 4; nt++) {
            const int cc = gcol0 + nt * 8;
            float2 bb = *(const float2*)(bias + cc);
            *(float2*)(dst + (size_t)rA * Ee + cc) =
                make_float2((acc[mt][nt][0] + bb.x) * scale, (acc[mt][nt][1] + bb.y) * scale);
            *(float2*)(dst + (size_t)rB * Ee + cc) =
                make_float2((acc[mt][nt][2] + bb.x) * scale, (acc[mt][nt][3] + bb.y) * scale);
        }
    }
}

// ---------------- K2: V transpose -> g_vt[hn][rd][j] ----------------
__global__ __launch_bounds__(256) void transpose_v_kernel()
{
    __shared__ float tile[32][33];
    const int t = threadIdx.x;
    const int tx = t & 31, a0 = t >> 5;
    const int jb = blockIdx.x, rdb = blockIdx.y, hn = blockIdx.z;
    const int h = hn / 12, n = hn % 12;
    const int r = rdb >> 1, d0 = (rdb & 1) * 32;
    #pragma unroll
    for (int i = 0; i < 4; i++) {
        int jl = a0 + 8 * i;
        int j = jb * 32 + jl;
        tile[jl][tx] = g_v[((size_t)(r * Cc + j) * Bb + n) * Ee + h * 64 + d0 + tx];
    }
    __syncthreads();
    #pragma unroll
    for (int i = 0; i < 4; i++) {
        int dl = a0 + 8 * i;
        g_vt[((size_t)hn * RD + rdb * 32 + dl) * Cc + jb * 32 + tx] = tile[tx][dl];
    }
}

// ---------------- K3: scores + bucket bias ----------------
__global__ __launch_bounds__(256) void scores_mma(const float* __restrict__ rel_bias)
{
    const int n0 = blockIdx.x * 128;
    const int m0 = blockIdx.y * 128;
    const int hn = blockIdx.z;
    const int h = hn / 12, n = hn % 12;

    GP P;
    {
        const int rl = threadIdx.x >> 3, c4 = threadIdx.x & 7;
        #pragma unroll
        for (int i = 0; i < 4; i++) {
            P.a[i] = (const float4*)(g_q + ((size_t)(m0 + rl + 32*i) * Bb + n) * Ee + h * 64) + c4;
            P.b[i] = (const float4*)(g_k + ((size_t)(n0 + rl + 32*i) * Bb + n) * Ee + h * 64) + c4;
        }
    }
    float acc[4][4][4];
    gemm_mma(P, 32, (long)Cc * Bb * Ee / 4, true, acc);

    EPI_IDX();
    #pragma unroll
    for (int mt = 0; mt < 4; mt++) {
        const int iA = grow0 + mt * 16, iB = iA + 8;
        const unsigned char* bA = g_buck + ((size_t)h * Cc + iA) * Cc;
        const unsigned char* bB = g_buck + ((size_t)h * Cc + iB) * Cc;
        float* sA = g_s + ((size_t)hn * Cc + iA) * Cc;
        float* sB = g_s + ((size_t)hn * Cc + iB) * Cc;
        #pragma unroll
        for (int nt = 0; nt < 4; nt++) {
            const int cc = gcol0 + nt * 8;
            *(float2*)(sA + cc) = make_float2(
                acc[mt][nt][0] + __ldg(&rel_bias[bA[cc]   * Hh + n]),
                acc[mt][nt][1] + __ldg(&rel_bias[bA[cc+1] * Hh + n]));
            *(float2*)(sB + cc) = make_float2(
                acc[mt][nt][2] + __ldg(&rel_bias[bB[cc]   * Hh + n]),
                acc[mt][nt][3] + __ldg(&rel_bias[bB[cc+1] * Hh + n]));
        }
    }
}

// ---------------- K4: softmax (rows of 256) ----------------
__global__ __launch_bounds__(256) void softmax_kernel()
{
    float* p = g_s + (size_t)blockIdx.x * Cc;
    const int t = threadIdx.x, lane = t & 31, w = t >> 5;
    __shared__ float red[8];
    float v = p[t];
    float m = v;
    #pragma unroll
    for (int o = 16; o > 0; o >>= 1) m = fmaxf(m, __shfl_xor_sync(~0u, m, o));
    if (lane == 0) red[w] = m;
    __syncthreads();
    if (w == 0) {
        float mm = red[lane & 7];
        #pragma unroll
        for (int o = 4; o > 0; o >>= 1) mm = fmaxf(mm, __shfl_xor_sync(~0u, mm, o));
        if (lane == 0) red[0] = mm;
    }
    __syncthreads();
    m = red[0];
    __syncthreads();
    float e = expf(v - m), s = e;
    #pragma unroll
    for (int o = 16; o > 0; o >>= 1) s += __shfl_xor_sync(~0u, s, o);
    if (lane == 0) red[w] = s;
    __syncthreads();
    if (w == 0) {
        float ss = red[lane & 7];
        #pragma unroll
        for (int o = 4; o > 0; o >>= 1) ss += __shfl_xor_sync(~0u, ss, o);
        if (lane == 0) red[0] = ss;
    }
    __syncthreads();
    p[t] = e / red[0];
}

// ---------------- K5: context = P @ Vt -> token layout ----------------
__global__ __launch_bounds__(256) void ctx_mma()
{
    const int n0 = blockIdx.x * 128;   // rd
    const int m0 = blockIdx.y * 128;   // i
    const int hn = blockIdx.z;
    const int h = hn / 12, n = hn % 12;

    GP P;
    {
        const int rl = threadIdx.x >> 3, c4 = threadIdx.x & 7;
        #pragma unroll
        for (int i = 0; i < 4; i++) {
            P.a[i] = (const float4*)(g_s  + ((size_t)hn * Cc + m0 + rl + 32*i) * Cc) + c4;
            P.b[i] = (const float4*)(g_vt + ((size_t)hn * RD + n0 + rl + 32*i) * Cc) + c4;
        }
    }
    float acc[4][4][4];
    gemm_mma(P, 8, 0, false, acc);

    EPI_IDX();
    #pragma unroll
    for (int mt = 0; mt < 4; mt++) {
        const int iA = grow0 + mt * 16, iB = iA + 8;
        #pragma unroll
        for (int nt = 0; nt < 4; nt++) {
            const int cc = gcol0 + nt * 8;
            const int r = cc >> 6, d = cc & 63;
            float* dA = g_ctx + (((size_t)(r * Cc + iA)) * Bb + n) * Ee + h * 64 + d;
            float* dB = g_ctx + (((size_t)(r * Cc + iB)) * Bb + n) * Ee + h * 64 + d;
            *(float2*)dA = make_float2(acc[mt][nt][0], acc[mt][nt][1]);
            *(float2*)dB = make_float2(acc[mt][nt][2], acc[mt][nt][3]);
        }
    }
}

// ---------------- K6: output projection ----------------
__global__ __launch_bounds__(256) void outproj_mma(
    const float* __restrict__ Wo, const float* __restrict__ bo, float* __restrict__ out)
{
    const int n0 = blockIdx.x * 128;
    const int m0 = blockIdx.y * 128;

    GP P;
    {
        const int rl = threadIdx.x >> 3, c4 = threadIdx.x & 7;
        #pragma unroll
        for (int i = 0; i < 4; i++) {
            P.a[i] = (const float4*)(g_ctx + (size_t)(m0 + rl + 32*i) * Ee) + c4;
            P.b[i] = (const float4*)(Wo    + (size_t)(n0 + rl + 32*i) * Ee) + c4;
        }
    }
    float acc[4][4][4];
    gemm_mma(P, 24, 0, false, acc);

    EPI_IDX();
    #pragma unroll
    for (int mt = 0; mt < 4; mt++) {
        const int rA = grow0 + mt * 16, rB = rA + 8;
        #pragma unroll
        for (int nt = 0; nt < 4; nt++) {
            const int cc = gcol0 + nt * 8;
            float2 bb = *(const float2*)(bo + cc);
            *(float2*)(out + (size_t)rA * Ee + cc) =
                make_float2(acc[mt][nt][0] + bb.x, acc[mt][nt][1] + bb.y);
            *(float2*)(out + (size_t)rB * Ee + cc) =
                make_float2(acc[mt][nt][2] + bb.x, acc[mt][nt][3] + bb.y);
        }
    }
}

__global__ __launch_bounds__(256) void copy_probs_kernel(float* __restrict__ dst)
{
    size_t idx = (size_t)blockIdx.x * 256 + threadIdx.x;
    ((float4*)dst)[idx] = ((const float4*)g_s)[idx];
}

// ---------------------------------------------------------------------------
extern "C" void kernel_launch(void* const* d_in, const int* in_sizes, int n_in,
                              void* d_out, int out_size)
{
    const float* x         = (const float*)d_in[0];
    const int*   distances = (const int*)  d_in[1];
    const float* Wq = (const float*)d_in[2];
    const float* bq = (const float*)d_in[3];
    const float* Wk = (const float*)d_in[4];
    const float* bk = (const float*)d_in[5];
    const float* Wv = (const float*)d_in[6];
    const float* bv = (const float*)d_in[7];
    const float* Wo = (const float*)d_in[8];
    const float* bo = (const float*)d_in[9];
    const float* rel_bias = (const float*)d_in[10];
    float* out = (float*)d_out;

    cudaFuncSetAttribute(proj_mma,    cudaFuncAttributeMaxDynamicSharedMemorySize, SMEM_DYN);
    cudaFuncSetAttribute(scores_mma,  cudaFuncAttributeMaxDynamicSharedMemorySize, SMEM_DYN);
    cudaFuncSetAttribute(ctx_mma,     cudaFuncAttributeMaxDynamicSharedMemorySize, SMEM_DYN);
    cudaFuncSetAttribute(outproj_mma, cudaFuncAttributeMaxDynamicSharedMemorySize, SMEM_DYN);

    bucketize_kernel<<<Hh*Cc*Cc/256, 256>>>(distances);
    proj_mma<<<dim3(6, NTOK/128, 3), 256, SMEM_DYN>>>(x, Wq, bq, Wk, bk, Wv, bv);
    transpose_v_kernel<<<dim3(8, 32, 144), 256>>>();
    scores_mma<<<dim3(2, 2, 144), 256, SMEM_DYN>>>(rel_bias);
    softmax_kernel<<<Hh*Bb*Cc, 256>>>();
    ctx_mma<<<dim3(8, 2, 144), 256, SMEM_DYN>>>();
    outproj_mma<<<dim3(6, NTOK/128), 256, SMEM_DYN>>>(Wo, bo, out);

    const size_t out_elems   = (size_t)NTOK * Ee;
    const size_t probs_elems = (size_t)Hh * Bb * Cc * Cc;
    if ((size_t)out_size >= out_elems + probs_elems) {
        copy_probs_kernel<<<(unsigned)(probs_elems / 4 / 256), 256>>>(out + out_elems);
    }
}

// round 5
// speedup vs baseline: 4.1061x; 1.4347x over previous
#include <cuda_runtime.h>
#include <cuda_bf16.h>
#include <math.h>
#include <stdint.h>

#define Rr   16
#define Cc   256
#define Bb   12
#define Ee   768
#define Hh   12
#define Dd   64
#define RD   1024
#define NTOK 49152
#define SCALING 0.03125f

// Scratch (tf32-rounded operands unless noted)
__device__ float g_xr [(size_t)NTOK*Ee];        // rounded x
__device__ float g_wr [4][(size_t)Ee*Ee];       // rounded Wq,Wk,Wv,Wo
__device__ float g_q  [(size_t)NTOK*Ee];        // rounded
__device__ float g_k  [(size_t)NTOK*Ee];        // rounded
__device__ float g_v  [(size_t)NTOK*Ee];        // rounded
__device__ float g_vt [(size_t)Hh*Bb*RD*Cc];    // rounded (copy of g_v)
__device__ float g_s  [(size_t)Hh*Bb*Cc*Cc];    // f32 scores/probs (output)
__device__ float g_sr [(size_t)Hh*Bb*Cc*Cc];    // rounded probs for ctx GEMM
__device__ float g_ctx[(size_t)NTOK*Ee];        // rounded
__device__ unsigned char g_buck[(size_t)Hh*Cc*Cc];

#define STAGE_BYTES 32768            // A 16KB + B 16KB
#define SMEM_DYN    (3*STAGE_BYTES)  // 3-stage pipeline

// ---------------- helpers ----------------
__device__ __forceinline__ uint32_t smem_u32(const void* p) {
    uint32_t a;
    asm("{ .reg .u64 t; cvta.to.shared.u64 t, %1; cvt.u32.u64 %0, t; }" : "=r"(a) : "l"(p));
    return a;
}
__device__ __forceinline__ float rna_f(float x) {
    uint32_t u;
    asm("cvt.rna.tf32.f32 %0, %1;" : "=r"(u) : "f"(x));
    return __uint_as_float(u);
}
__device__ __forceinline__ float4 rna4(float4 v) {
    return make_float4(rna_f(v.x), rna_f(v.y), rna_f(v.z), rna_f(v.w));
}
#define CP_ASYNC16(d, s) \
    asm volatile("cp.async.cg.shared.global [%0], [%1], 16;" :: "r"(d), "l"(s) : "memory")
#define CP_COMMIT() asm volatile("cp.async.commit_group;" ::: "memory")
#define CP_WAIT1()  asm volatile("cp.async.wait_group 1;" ::: "memory")
#define LDSM4(r, addr) \
    asm volatile("ldmatrix.sync.aligned.m8n8.x4.shared.b16 {%0,%1,%2,%3}, [%4];" \
        : "=r"((r)[0]), "=r"((r)[1]), "=r"((r)[2]), "=r"((r)[3]) : "r"(addr))
#define MMA_TF32(d, a, b) \
    asm volatile("mma.sync.aligned.m16n8k8.row.col.f32.tf32.tf32.f32 " \
        "{%0,%1,%2,%3}, {%4,%5,%6,%7}, {%8,%9}, {%0,%1,%2,%3};" \
        : "+f"((d)[0]), "+f"((d)[1]), "+f"((d)[2]), "+f"((d)[3]) \
        : "r"((a)[0]), "r"((a)[1]), "r"((a)[2]), "r"((a)[3]), \
          "r"((b)[0]), "r"((b)[1]))

// ---------------- shared GEMM core ----------------
// Block 128(M) x 128(N), K-chunk = 32 f32 (128 bytes per row), both operands
// K-contiguous (NT).  SMEM tile rows XOR-16B swizzled.  cp.async 3-stage.
__device__ __forceinline__ void gemm_mma_async(
    const char* a0, const char* b0, long arow, long brow,
    int NC, long roff, bool split, float acc[4][4][4])
{
    extern __shared__ uint32_t smem[];
    const uint32_t sbase = smem_u32(smem);
    const int t = threadIdx.x;
    const int lane = t & 31, wid = t >> 5;
    const int wm = wid >> 2, wn = wid & 3;

    uint32_t sts[4];
    {
        const int c16 = t & 7;
        #pragma unroll
        for (int i = 0; i < 4; i++) {
            int row = (t >> 3) + 32 * i;
            sts[i] = (uint32_t)(row * 128 + ((c16 ^ (row & 7)) << 4));
        }
    }
    #pragma unroll
    for (int mt = 0; mt < 4; mt++)
        #pragma unroll
        for (int nt = 0; nt < 4; nt++)
            #pragma unroll
            for (int r = 0; r < 4; r++) acc[mt][nt][r] = 0.0f;

    // prologue: stages 0,1
    #pragma unroll
    for (int s = 0; s < 2; s++) {
        const long o = split ? ((long)(s >> 1) * roff + (long)(s & 1) * 128) : (long)s * 128;
        const uint32_t d = sbase + (uint32_t)s * STAGE_BYTES;
        #pragma unroll
        for (int i = 0; i < 4; i++) {
            CP_ASYNC16(d + sts[i],          a0 + i * arow + o);
            CP_ASYNC16(d + 16384u + sts[i], b0 + i * brow + o);
        }
        CP_COMMIT();
    }

    int sc = 0;   // stage index of chunk c (c % 3)
    for (int c = 0; c < NC; c++) {
        CP_WAIT1();
        __syncthreads();
        if (c + 2 < NC) {
            const int cn = c + 2;
            const long o = split ? ((long)(cn >> 1) * roff + (long)(cn & 1) * 128)
                                 : (long)cn * 128;
            int sn = sc + 2; if (sn >= 3) sn -= 3;
            const uint32_t d = sbase + (uint32_t)sn * STAGE_BYTES;
            #pragma unroll
            for (int i = 0; i < 4; i++) {
                CP_ASYNC16(d + sts[i],          a0 + i * arow + o);
                CP_ASYNC16(d + 16384u + sts[i], b0 + i * brow + o);
            }
            CP_COMMIT();
        } else {
            CP_COMMIT();   // keep group accounting uniform
        }

        const uint32_t sa = sbase + (uint32_t)sc * STAGE_BYTES;
        const uint32_t sb = sa + 16384u;
        #pragma unroll
        for (int ks = 0; ks < 4; ks++) {
            uint32_t af[4][4], bf[4][2];
            #pragma unroll
            for (int mt = 0; mt < 4; mt++) {
                int row = wm * 64 + mt * 16 + (lane & 15);
                int c16 = ks * 2 + (lane >> 4);
                LDSM4(af[mt], sa + row * 128 + ((c16 ^ (row & 7)) << 4));
            }
            #pragma unroll
            for (int p = 0; p < 2; p++) {
                int mm = lane >> 3;
                int row = wn * 32 + p * 16 + ((mm >> 1) << 3) + (lane & 7);
                int c16 = ks * 2 + (mm & 1);
                uint32_t r4[4];
                LDSM4(r4, sb + row * 128 + ((c16 ^ (row & 7)) << 4));
                bf[2*p+0][0] = r4[0]; bf[2*p+0][1] = r4[1];
                bf[2*p+1][0] = r4[2]; bf[2*p+1][1] = r4[3];
            }
            #pragma unroll
            for (int mt = 0; mt < 4; mt++)
                #pragma unroll
                for (int nt = 0; nt < 4; nt++)
                    MMA_TF32(acc[mt][nt], af[mt], bf[nt]);
        }
        if (++sc == 3) sc = 0;
    }
}

#define EPI_IDX()                                                         \
    const int lane = threadIdx.x & 31, wid = threadIdx.x >> 5;            \
    const int wm = wid >> 2, wn = wid & 3;                                \
    const int grow0 = m0 + wm * 64 + (lane >> 2);                         \
    const int gcol0 = n0 + wn * 32 + (lane & 3) * 2;

// ---------------- small kernels ----------------
__device__ __forceinline__ int rel_bucket(int dist) {
    if (dist < 16) return dist;
    float v = logf(fmaxf((float)dist, 1.0f) * 0.0625f) * (15.0f / 8.047189562170502f);
    int b = 16 + (int)v;
    return b < 31 ? b : 31;
}
__global__ __launch_bounds__(256) void bucketize_kernel(const int* __restrict__ dist) {
    size_t i = (size_t)blockIdx.x * 256 + threadIdx.x;
    g_buck[i] = (unsigned char)rel_bucket(__ldg(&dist[i]));
}
__global__ __launch_bounds__(256) void round4_kernel(const float4* __restrict__ src,
                                                     float4* __restrict__ dst) {
    size_t i = (size_t)blockIdx.x * 256 + threadIdx.x;
    dst[i] = rna4(__ldg(&src[i]));
}

// ---------------- K1: QKV projection ----------------
__global__ __launch_bounds__(256, 2) void proj_mma(
    const float* __restrict__ bq, const float* __restrict__ bk, const float* __restrict__ bv)
{
    const int w  = blockIdx.z;
    const int n0 = blockIdx.x * 128;
    const int m0 = blockIdx.y * 128;
    const float* bias = (w == 0) ? bq : (w == 1) ? bk : bv;
    float*       dst  = (w == 0) ? g_q : (w == 1) ? g_k : g_v;
    const float  scale = (w == 0) ? SCALING : 1.0f;

    const int rl = threadIdx.x >> 3, c4 = threadIdx.x & 7;
    const char* a0 = (const char*)(g_xr + (size_t)(m0 + rl) * Ee) + c4 * 16;
    const char* b0 = (const char*)(g_wr[w] + (size_t)(n0 + rl) * Ee) + c4 * 16;

    float acc[4][4][4];
    gemm_mma_async(a0, b0, 32L*Ee*4, 32L*Ee*4, 24, 0, false, acc);

    EPI_IDX();
    #pragma unroll
    for (int mt = 0; mt < 4; mt++) {
        const int rA = grow0 + mt * 16, rB = rA + 8;
        #pragma unroll
        for (int nt = 0; nt < 4; nt++) {
            const int cc = gcol0 + nt * 8;
            float2 bb = *(const float2*)(bias + cc);
            *(float2*)(dst + (size_t)rA * Ee + cc) = make_float2(
                rna_f((acc[mt][nt][0] + bb.x) * scale), rna_f((acc[mt][nt][1] + bb.y) * scale));
            *(float2*)(dst + (size_t)rB * Ee + cc) = make_float2(
                rna_f((acc[mt][nt][2] + bb.x) * scale), rna_f((acc[mt][nt][3] + bb.y) * scale));
        }
    }
}

// ---------------- K2: V transpose -> g_vt[hn][rd][j] ----------------
__global__ __launch_bounds__(256) void transpose_v_kernel()
{
    __shared__ float tile[32][33];
    const int t = threadIdx.x;
    const int tx = t & 31, a0 = t >> 5;
    const int jb = blockIdx.x, rdb = blockIdx.y, hn = blockIdx.z;
    const int h = hn / 12, n = hn % 12;
    const int r = rdb >> 1, d0 = (rdb & 1) * 32;
    #pragma unroll
    for (int i = 0; i < 4; i++) {
        int jl = a0 + 8 * i;
        int j = jb * 32 + jl;
        tile[jl][tx] = g_v[((size_t)(r * Cc + j) * Bb + n) * Ee + h * 64 + d0 + tx];
    }
    __syncthreads();
    #pragma unroll
    for (int i = 0; i < 4; i++) {
        int dl = a0 + 8 * i;
        g_vt[((size_t)hn * RD + rdb * 32 + dl) * Cc + jb * 32 + tx] = tile[tx][dl];
    }
}

// ---------------- K3: scores + bucket bias ----------------
__global__ __launch_bounds__(256, 2) void scores_mma(const float* __restrict__ rel_bias)
{
    const int n0 = blockIdx.x * 128;
    const int m0 = blockIdx.y * 128;
    const int hn = blockIdx.z;
    const int h = hn / 12, n = hn % 12;

    const int rl = threadIdx.x >> 3, c4 = threadIdx.x & 7;
    const char* a0 = (const char*)(g_q + ((size_t)(m0 + rl) * Bb + n) * Ee + h * 64) + c4 * 16;
    const char* b0 = (const char*)(g_k + ((size_t)(n0 + rl) * Bb + n) * Ee + h * 64) + c4 * 16;

    float acc[4][4][4];
    gemm_mma_async(a0, b0, 32L*Bb*Ee*4, 32L*Bb*Ee*4, 32, (long)Cc*Bb*Ee*4, true, acc);

    EPI_IDX();
    #pragma unroll
    for (int mt = 0; mt < 4; mt++) {
        const int iA = grow0 + mt * 16, iB = iA + 8;
        const unsigned char* bA = g_buck + ((size_t)h * Cc + iA) * Cc;
        const unsigned char* bB = g_buck + ((size_t)h * Cc + iB) * Cc;
        float* sA = g_s + ((size_t)hn * Cc + iA) * Cc;
        float* sB = g_s + ((size_t)hn * Cc + iB) * Cc;
        #pragma unroll
        for (int nt = 0; nt < 4; nt++) {
            const int cc = gcol0 + nt * 8;
            *(float2*)(sA + cc) = make_float2(
                acc[mt][nt][0] + __ldg(&rel_bias[bA[cc]   * Hh + n]),
                acc[mt][nt][1] + __ldg(&rel_bias[bA[cc+1] * Hh + n]));
            *(float2*)(sB + cc) = make_float2(
                acc[mt][nt][2] + __ldg(&rel_bias[bB[cc]   * Hh + n]),
                acc[mt][nt][3] + __ldg(&rel_bias[bB[cc+1] * Hh + n]));
        }
    }
}

// ---------------- K4: softmax (rows of 256); writes f32 + rounded copy ----
__global__ __launch_bounds__(256) void softmax_kernel()
{
    float* p  = g_s  + (size_t)blockIdx.x * Cc;
    float* pr = g_sr + (size_t)blockIdx.x * Cc;
    const int t = threadIdx.x, lane = t & 31, w = t >> 5;
    __shared__ float red[8];
    float v = p[t];
    float m = v;
    #pragma unroll
    for (int o = 16; o > 0; o >>= 1) m = fmaxf(m, __shfl_xor_sync(~0u, m, o));
    if (lane == 0) red[w] = m;
    __syncthreads();
    if (w == 0) {
        float mm = red[lane & 7];
        #pragma unroll
        for (int o = 4; o > 0; o >>= 1) mm = fmaxf(mm, __shfl_xor_sync(~0u, mm, o));
        if (lane == 0) red[0] = mm;
    }
    __syncthreads();
    m = red[0];
    __syncthreads();
    float e = expf(v - m), s = e;
    #pragma unroll
    for (int o = 16; o > 0; o >>= 1) s += __shfl_xor_sync(~0u, s, o);
    if (lane == 0) red[w] = s;
    __syncthreads();
    if (w == 0) {
        float ss = red[lane & 7];
        #pragma unroll
        for (int o = 4; o > 0; o >>= 1) ss += __shfl_xor_sync(~0u, ss, o);
        if (lane == 0) red[0] = ss;
    }
    __syncthreads();
    float prob = e / red[0];
    p[t]  = prob;
    pr[t] = rna_f(prob);
}

// ---------------- K5: context = P @ Vt -> token layout (rounded) --------
__global__ __launch_bounds__(256, 2) void ctx_mma()
{
    const int n0 = blockIdx.x * 128;   // rd
    const int m0 = blockIdx.y * 128;   // i
    const int hn = blockIdx.z;
    const int h = hn / 12, n = hn % 12;

    const int rl = threadIdx.x >> 3, c4 = threadIdx.x & 7;
    const char* a0 = (const char*)(g_sr + ((size_t)hn * Cc + m0 + rl) * Cc) + c4 * 16;
    const char* b0 = (const char*)(g_vt + ((size_t)hn * RD + n0 + rl) * Cc) + c4 * 16;

    float acc[4][4][4];
    gemm_mma_async(a0, b0, 32L*Cc*4, 32L*Cc*4, 8, 0, false, acc);

    EPI_IDX();
    #pragma unroll
    for (int mt = 0; mt < 4; mt++) {
        const int iA = grow0 + mt * 16, iB = iA + 8;
        #pragma unroll
        for (int nt = 0; nt < 4; nt++) {
            const int cc = gcol0 + nt * 8;
            const int r = cc >> 6, d = cc & 63;
            float* dA = g_ctx + (((size_t)(r * Cc + iA)) * Bb + n) * Ee + h * 64 + d;
            float* dB = g_ctx + (((size_t)(r * Cc + iB)) * Bb + n) * Ee + h * 64 + d;
            *(float2*)dA = make_float2(rna_f(acc[mt][nt][0]), rna_f(acc[mt][nt][1]));
            *(float2*)dB = make_float2(rna_f(acc[mt][nt][2]), rna_f(acc[mt][nt][3]));
        }
    }
}

// ---------------- K6: output projection ----------------
__global__ __launch_bounds__(256, 2) void outproj_mma(
    const float* __restrict__ bo, float* __restrict__ out)
{
    const int n0 = blockIdx.x * 128;
    const int m0 = blockIdx.y * 128;

    const int rl = threadIdx.x >> 3, c4 = threadIdx.x & 7;
    const char* a0 = (const char*)(g_ctx + (size_t)(m0 + rl) * Ee) + c4 * 16;
    const char* b0 = (const char*)(g_wr[3] + (size_t)(n0 + rl) * Ee) + c4 * 16;

    float acc[4][4][4];
    gemm_mma_async(a0, b0, 32L*Ee*4, 32L*Ee*4, 24, 0, false, acc);

    EPI_IDX();
    #pragma unroll
    for (int mt = 0; mt < 4; mt++) {
        const int rA = grow0 + mt * 16, rB = rA + 8;
        #pragma unroll
        for (int nt = 0; nt < 4; nt++) {
            const int cc = gcol0 + nt * 8;
            float2 bb = *(const float2*)(bo + cc);
            *(float2*)(out + (size_t)rA * Ee + cc) =
                make_float2(acc[mt][nt][0] + bb.x, acc[mt][nt][1] + bb.y);
            *(float2*)(out + (size_t)rB * Ee + cc) =
                make_float2(acc[mt][nt][2] + bb.x, acc[mt][nt][3] + bb.y);
        }
    }
}

__global__ __launch_bounds__(256) void copy_probs_kernel(float* __restrict__ dst)
{
    size_t idx = (size_t)blockIdx.x * 256 + threadIdx.x;
    ((float4*)dst)[idx] = ((const float4*)g_s)[idx];
}

// ---------------------------------------------------------------------------
extern "C" void kernel_launch(void* const* d_in, const int* in_sizes, int n_in,
                              void* d_out, int out_size)
{
    const float* x         = (const float*)d_in[0];
    const int*   distances = (const int*)  d_in[1];
    const float* Wq = (const float*)d_in[2];
    const float* bq = (const float*)d_in[3];
    const float* Wk = (const float*)d_in[4];
    const float* bk = (const float*)d_in[5];
    const float* Wv = (const float*)d_in[6];
    const float* bv = (const float*)d_in[7];
    const float* Wo = (const float*)d_in[8];
    const float* bo = (const float*)d_in[9];
    const float* rel_bias = (const float*)d_in[10];
    float* out = (float*)d_out;

    cudaFuncSetAttribute(proj_mma,    cudaFuncAttributeMaxDynamicSharedMemorySize, SMEM_DYN);
    cudaFuncSetAttribute(scores_mma,  cudaFuncAttributeMaxDynamicSharedMemorySize, SMEM_DYN);
    cudaFuncSetAttribute(ctx_mma,     cudaFuncAttributeMaxDynamicSharedMemorySize, SMEM_DYN);
    cudaFuncSetAttribute(outproj_mma, cudaFuncAttributeMaxDynamicSharedMemorySize, SMEM_DYN);

    float* d_xr;  cudaGetSymbolAddress((void**)&d_xr, g_xr);
    float* d_wr;  cudaGetSymbolAddress((void**)&d_wr, g_wr);

    // Pre-round operands to tf32 bit patterns (RNA)
    round4_kernel<<<(unsigned)((size_t)NTOK*Ee/4/256), 256>>>((const float4*)x, (float4*)d_xr);
    round4_kernel<<<Ee*Ee/4/256, 256>>>((const float4*)Wq, (float4*)(d_wr + 0*(size_t)Ee*Ee));
    round4_kernel<<<Ee*Ee/4/256, 256>>>((const float4*)Wk, (float4*)(d_wr + 1*(size_t)Ee*Ee));
    round4_kernel<<<Ee*Ee/4/256, 256>>>((const float4*)Wv, (float4*)(d_wr + 2*(size_t)Ee*Ee));
    round4_kernel<<<Ee*Ee/4/256, 256>>>((const float4*)Wo, (float4*)(d_wr + 3*(size_t)Ee*Ee));
    bucketize_kernel<<<Hh*Cc*Cc/256, 256>>>(distances);

    proj_mma<<<dim3(6, NTOK/128, 3), 256, SMEM_DYN>>>(bq, bk, bv);
    transpose_v_kernel<<<dim3(8, 32, 144), 256>>>();
    scores_mma<<<dim3(2, 2, 144), 256, SMEM_DYN>>>(rel_bias);
    softmax_kernel<<<Hh*Bb*Cc, 256>>>();
    ctx_mma<<<dim3(8, 2, 144), 256, SMEM_DYN>>>();
    outproj_mma<<<dim3(6, NTOK/128), 256, SMEM_DYN>>>(bo, out);

    const size_t out_elems   = (size_t)NTOK * Ee;
    const size_t probs_elems = (size_t)Hh * Bb * Cc * Cc;
    if ((size_t)out_size >= out_elems + probs_elems) {
        copy_probs_kernel<<<(unsigned)(probs_elems / 4 / 256), 256>>>(out + out_elems);
    }
}

// round 6
// speedup vs baseline: 4.1640x; 1.0141x over previous
#include <cuda_runtime.h>
#include <cuda_bf16.h>
#include <math.h>
#include <stdint.h>

#define Rr   16
#define Cc   256
#define Bb   12
#define Ee   768
#define Hh   12
#define Dd   64
#define RD   1024
#define NTOK 49152
#define SCALING 0.03125f

// Scratch (tf32-rounded operands unless noted)
__device__ float g_xr [(size_t)NTOK*Ee];
__device__ float g_wr [4][(size_t)Ee*Ee];
__device__ float g_q  [(size_t)NTOK*Ee];
__device__ float g_k  [(size_t)NTOK*Ee];
__device__ float g_v  [(size_t)NTOK*Ee];
__device__ float g_vt [(size_t)Hh*Bb*RD*Cc];
__device__ float g_s  [(size_t)Hh*Bb*Cc*Cc];    // f32 scores (softmax input)
__device__ float g_sr [(size_t)Hh*Bb*Cc*Cc];    // rounded probs for ctx GEMM
__device__ float g_ctx[(size_t)NTOK*Ee];
__device__ unsigned char g_buck[(size_t)Hh*Cc*Cc];

#define STAGE_BYTES 32768            // A 16KB + B 16KB
#define SMEM_DYN    (3*STAGE_BYTES)  // 3-stage pipeline

// ---------------- helpers ----------------
__device__ __forceinline__ uint32_t smem_u32(const void* p) {
    uint32_t a;
    asm("{ .reg .u64 t; cvta.to.shared.u64 t, %1; cvt.u32.u64 %0, t; }" : "=r"(a) : "l"(p));
    return a;
}
__device__ __forceinline__ float rna_f(float x) {
    uint32_t u;
    asm("cvt.rna.tf32.f32 %0, %1;" : "=r"(u) : "f"(x));
    return __uint_as_float(u);
}
__device__ __forceinline__ float4 rna4(float4 v) {
    return make_float4(rna_f(v.x), rna_f(v.y), rna_f(v.z), rna_f(v.w));
}
#define CP_ASYNC16(d, s) \
    asm volatile("cp.async.cg.shared.global [%0], [%1], 16;" :: "r"(d), "l"(s) : "memory")
#define CP_COMMIT() asm volatile("cp.async.commit_group;" ::: "memory")
#define CP_WAIT1()  asm volatile("cp.async.wait_group 1;" ::: "memory")
#define LDSM4(r, addr) \
    asm volatile("ldmatrix.sync.aligned.m8n8.x4.shared.b16 {%0,%1,%2,%3}, [%4];" \
        : "=r"((r)[0]), "=r"((r)[1]), "=r"((r)[2]), "=r"((r)[3]) : "r"(addr))
#define MMA_TF32(d, a, b) \
    asm volatile("mma.sync.aligned.m16n8k8.row.col.f32.tf32.tf32.f32 " \
        "{%0,%1,%2,%3}, {%4,%5,%6,%7}, {%8,%9}, {%0,%1,%2,%3};" \
        : "+f"((d)[0]), "+f"((d)[1]), "+f"((d)[2]), "+f"((d)[3]) \
        : "r"((a)[0]), "r"((a)[1]), "r"((a)[2]), "r"((a)[3]), \
          "r"((b)[0]), "r"((b)[1]))

// ---------------- shared GEMM core ----------------
// Block 128(M) x 128(N), K-chunk = 32 f32 (128B/row), both operands K-contig.
// SMEM rows XOR-16B swizzled.  3-stage cp.async.  LDSM offsets precomputed
// relative to the stage base (loop-invariant -> registers, ALU off the hot loop).
__device__ __forceinline__ void gemm_mma_async(
    const char* a0, const char* b0, long arow, long brow,
    int NC, long roff, bool split, float acc[4][4][4])
{
    extern __shared__ uint32_t smem[];
    const uint32_t sbase = smem_u32(smem);
    const int t = threadIdx.x;
    const int lane = t & 31, wid = t >> 5;
    const int wm = wid >> 2, wn = wid & 3;

    uint32_t sts[4];
    {
        const int c16 = t & 7;
        #pragma unroll
        for (int i = 0; i < 4; i++) {
            int row = (t >> 3) + 32 * i;
            sts[i] = (uint32_t)(row * 128 + ((c16 ^ (row & 7)) << 4));
        }
    }
    // Precomputed LDSM offsets (relative to stage base)
    uint32_t arel[4][4];   // [mt][ks]
    uint32_t brel[4][2];   // [ks][p], +16384 folded in
    {
        #pragma unroll
        for (int mt = 0; mt < 4; mt++) {
            int row = wm * 64 + mt * 16 + (lane & 15);
            #pragma unroll
            for (int ks = 0; ks < 4; ks++) {
                int c16 = ks * 2 + (lane >> 4);
                arel[mt][ks] = (uint32_t)(row * 128 + ((c16 ^ (row & 7)) << 4));
            }
        }
        const int mm = lane >> 3;
        #pragma unroll
        for (int p = 0; p < 2; p++) {
            int row = wn * 32 + p * 16 + ((mm >> 1) << 3) + (lane & 7);
            #pragma unroll
            for (int ks = 0; ks < 4; ks++) {
                int c16 = ks * 2 + (mm & 1);
                brel[ks][p] = (uint32_t)(16384 + row * 128 + ((c16 ^ (row & 7)) << 4));
            }
        }
    }
    #pragma unroll
    for (int mt = 0; mt < 4; mt++)
        #pragma unroll
        for (int nt = 0; nt < 4; nt++)
            #pragma unroll
            for (int r = 0; r < 4; r++) acc[mt][nt][r] = 0.0f;

    // prologue: stages 0,1
    #pragma unroll
    for (int s = 0; s < 2; s++) {
        const long o = split ? ((long)(s >> 1) * roff + (long)(s & 1) * 128) : (long)s * 128;
        const uint32_t d = sbase + (uint32_t)s * STAGE_BYTES;
        #pragma unroll
        for (int i = 0; i < 4; i++) {
            CP_ASYNC16(d + sts[i],          a0 + i * arow + o);
            CP_ASYNC16(d + 16384u + sts[i], b0 + i * brow + o);
        }
        CP_COMMIT();
    }

    int sc = 0;
    for (int c = 0; c < NC; c++) {
        CP_WAIT1();
        __syncthreads();
        if (c + 2 < NC) {
            const int cn = c + 2;
            const long o = split ? ((long)(cn >> 1) * roff + (long)(cn & 1) * 128)
                                 : (long)cn * 128;
            int sn = sc + 2; if (sn >= 3) sn -= 3;
            const uint32_t d = sbase + (uint32_t)sn * STAGE_BYTES;
            #pragma unroll
            for (int i = 0; i < 4; i++) {
                CP_ASYNC16(d + sts[i],          a0 + i * arow + o);
                CP_ASYNC16(d + 16384u + sts[i], b0 + i * brow + o);
            }
            CP_COMMIT();
        } else {
            CP_COMMIT();
        }

        const uint32_t sa = sbase + (uint32_t)sc * STAGE_BYTES;
        #pragma unroll
        for (int ks = 0; ks < 4; ks++) {
            uint32_t af[4][4], bf[4][2];
            #pragma unroll
            for (int mt = 0; mt < 4; mt++) LDSM4(af[mt], sa + arel[mt][ks]);
            #pragma unroll
            for (int p = 0; p < 2; p++) {
                uint32_t r4[4];
                LDSM4(r4, sa + brel[ks][p]);
                bf[2*p+0][0] = r4[0]; bf[2*p+0][1] = r4[1];
                bf[2*p+1][0] = r4[2]; bf[2*p+1][1] = r4[3];
            }
            #pragma unroll
            for (int mt = 0; mt < 4; mt++)
                #pragma unroll
                for (int nt = 0; nt < 4; nt++)
                    MMA_TF32(acc[mt][nt], af[mt], bf[nt]);
        }
        if (++sc == 3) sc = 0;
    }
}

#define EPI_IDX()                                                         \
    const int lane = threadIdx.x & 31, wid = threadIdx.x >> 5;            \
    const int wm = wid >> 2, wn = wid & 3;                                \
    const int grow0 = m0 + wm * 64 + (lane >> 2);                         \
    const int gcol0 = n0 + wn * 32 + (lane & 3) * 2;

// ---------------- small kernels ----------------
__device__ __forceinline__ int rel_bucket(int dist) {
    if (dist < 16) return dist;
    float v = logf(fmaxf((float)dist, 1.0f) * 0.0625f) * (15.0f / 8.047189562170502f);
    int b = 16 + (int)v;
    return b < 31 ? b : 31;
}
__global__ __launch_bounds__(256) void bucketize_kernel(const int* __restrict__ dist) {
    size_t i = (size_t)blockIdx.x * 256 + threadIdx.x;
    g_buck[i] = (unsigned char)rel_bucket(__ldg(&dist[i]));
}
__global__ __launch_bounds__(256) void round4_kernel(const float4* __restrict__ src,
                                                     float4* __restrict__ dst) {
    size_t i = (size_t)blockIdx.x * 256 + threadIdx.x;
    dst[i] = rna4(__ldg(&src[i]));
}

// ---------------- K1: QKV projection ----------------
__global__ __launch_bounds__(256, 2) void proj_mma(
    const float* __restrict__ bq, const float* __restrict__ bk, const float* __restrict__ bv)
{
    const int w  = blockIdx.z;
    const int n0 = blockIdx.x * 128;
    const int m0 = blockIdx.y * 128;
    const float* bias = (w == 0) ? bq : (w == 1) ? bk : bv;
    float*       dst  = (w == 0) ? g_q : (w == 1) ? g_k : g_v;
    const float  scale = (w == 0) ? SCALING : 1.0f;

    const int rl = threadIdx.x >> 3, c4 = threadIdx.x & 7;
    const char* a0 = (const char*)(g_xr + (size_t)(m0 + rl) * Ee) + c4 * 16;
    const char* b0 = (const char*)(g_wr[w] + (size_t)(n0 + rl) * Ee) + c4 * 16;

    float acc[4][4][4];
    gemm_mma_async(a0, b0, 32L*Ee*4, 32L*Ee*4, 24, 0, false, acc);

    EPI_IDX();
    #pragma unroll
    for (int mt = 0; mt < 4; mt++) {
        const int rA = grow0 + mt * 16, rB = rA + 8;
        #pragma unroll
        for (int nt = 0; nt < 4; nt++) {
            const int cc = gcol0 + nt * 8;
            float2 bb = *(const float2*)(bias + cc);
            *(float2*)(dst + (size_t)rA * Ee + cc) = make_float2(
                rna_f((acc[mt][nt][0] + bb.x) * scale), rna_f((acc[mt][nt][1] + bb.y) * scale));
            *(float2*)(dst + (size_t)rB * Ee + cc) = make_float2(
                rna_f((acc[mt][nt][2] + bb.x) * scale), rna_f((acc[mt][nt][3] + bb.y) * scale));
        }
    }
}

// ---------------- K2: V transpose -> g_vt[hn][rd][j] ----------------
__global__ __launch_bounds__(256) void transpose_v_kernel()
{
    __shared__ float tile[32][33];
    const int t = threadIdx.x;
    const int tx = t & 31, a0 = t >> 5;
    const int jb = blockIdx.x, rdb = blockIdx.y, hn = blockIdx.z;
    const int h = hn / 12, n = hn % 12;
    const int r = rdb >> 1, d0 = (rdb & 1) * 32;
    #pragma unroll
    for (int i = 0; i < 4; i++) {
        int jl = a0 + 8 * i;
        int j = jb * 32 + jl;
        tile[jl][tx] = g_v[((size_t)(r * Cc + j) * Bb + n) * Ee + h * 64 + d0 + tx];
    }
    __syncthreads();
    #pragma unroll
    for (int i = 0; i < 4; i++) {
        int dl = a0 + 8 * i;
        g_vt[((size_t)hn * RD + rdb * 32 + dl) * Cc + jb * 32 + tx] = tile[tx][dl];
    }
}

// ---------------- K3: scores + bucket bias ----------------
__global__ __launch_bounds__(256, 2) void scores_mma(const float* __restrict__ rel_bias)
{
    const int n0 = blockIdx.x * 128;
    const int m0 = blockIdx.y * 128;
    const int hn = blockIdx.z;
    const int h = hn / 12, n = hn % 12;

    const int rl = threadIdx.x >> 3, c4 = threadIdx.x & 7;
    const char* a0 = (const char*)(g_q + ((size_t)(m0 + rl) * Bb + n) * Ee + h * 64) + c4 * 16;
    const char* b0 = (const char*)(g_k + ((size_t)(n0 + rl) * Bb + n) * Ee + h * 64) + c4 * 16;

    float acc[4][4][4];
    gemm_mma_async(a0, b0, 32L*Bb*Ee*4, 32L*Bb*Ee*4, 32, (long)Cc*Bb*Ee*4, true, acc);

    EPI_IDX();
    #pragma unroll
    for (int mt = 0; mt < 4; mt++) {
        const int iA = grow0 + mt * 16, iB = iA + 8;
        const unsigned char* bA = g_buck + ((size_t)h * Cc + iA) * Cc;
        const unsigned char* bB = g_buck + ((size_t)h * Cc + iB) * Cc;
        float* sA = g_s + ((size_t)hn * Cc + iA) * Cc;
        float* sB = g_s + ((size_t)hn * Cc + iB) * Cc;
        #pragma unroll
        for (int nt = 0; nt < 4; nt++) {
            const int cc = gcol0 + nt * 8;
            *(float2*)(sA + cc) = make_float2(
                acc[mt][nt][0] + __ldg(&rel_bias[bA[cc]   * Hh + n]),
                acc[mt][nt][1] + __ldg(&rel_bias[bA[cc+1] * Hh + n]));
            *(float2*)(sB + cc) = make_float2(
                acc[mt][nt][2] + __ldg(&rel_bias[bB[cc]   * Hh + n]),
                acc[mt][nt][3] + __ldg(&rel_bias[bB[cc+1] * Hh + n]));
        }
    }
}

// ---------------- K4: softmax; probs -> dst (d_out tail) + rounded copy ----
__global__ __launch_bounds__(256) void softmax_kernel(float* __restrict__ dst)
{
    const float* p = g_s + (size_t)blockIdx.x * Cc;
    float* pd = dst  + (size_t)blockIdx.x * Cc;
    float* pr = g_sr + (size_t)blockIdx.x * Cc;
    const int t = threadIdx.x, lane = t & 31, w = t >> 5;
    __shared__ float red[8];
    float v = p[t];
    float m = v;
    #pragma unroll
    for (int o = 16; o > 0; o >>= 1) m = fmaxf(m, __shfl_xor_sync(~0u, m, o));
    if (lane == 0) red[w] = m;
    __syncthreads();
    if (w == 0) {
        float mm = red[lane & 7];
        #pragma unroll
        for (int o = 4; o > 0; o >>= 1) mm = fmaxf(mm, __shfl_xor_sync(~0u, mm, o));
        if (lane == 0) red[0] = mm;
    }
    __syncthreads();
    m = red[0];
    __syncthreads();
    float e = expf(v - m), s = e;
    #pragma unroll
    for (int o = 16; o > 0; o >>= 1) s += __shfl_xor_sync(~0u, s, o);
    if (lane == 0) red[w] = s;
    __syncthreads();
    if (w == 0) {
        float ss = red[lane & 7];
        #pragma unroll
        for (int o = 4; o > 0; o >>= 1) ss += __shfl_xor_sync(~0u, ss, o);
        if (lane == 0) red[0] = ss;
    }
    __syncthreads();
    float prob = e / red[0];
    pd[t] = prob;
    pr[t] = rna_f(prob);
}

// ---------------- K5: context = P @ Vt -> token layout (rounded) --------
__global__ __launch_bounds__(256, 2) void ctx_mma()
{
    const int n0 = blockIdx.x * 128;   // rd
    const int m0 = blockIdx.y * 128;   // i
    const int hn = blockIdx.z;
    const int h = hn / 12, n = hn % 12;

    const int rl = threadIdx.x >> 3, c4 = threadIdx.x & 7;
    const char* a0 = (const char*)(g_sr + ((size_t)hn * Cc + m0 + rl) * Cc) + c4 * 16;
    const char* b0 = (const char*)(g_vt + ((size_t)hn * RD + n0 + rl) * Cc) + c4 * 16;

    float acc[4][4][4];
    gemm_mma_async(a0, b0, 32L*Cc*4, 32L*Cc*4, 8, 0, false, acc);

    EPI_IDX();
    #pragma unroll
    for (int mt = 0; mt < 4; mt++) {
        const int iA = grow0 + mt * 16, iB = iA + 8;
        #pragma unroll
        for (int nt = 0; nt < 4; nt++) {
            const int cc = gcol0 + nt * 8;
            const int r = cc >> 6, d = cc & 63;
            float* dA = g_ctx + (((size_t)(r * Cc + iA)) * Bb + n) * Ee + h * 64 + d;
            float* dB = g_ctx + (((size_t)(r * Cc + iB)) * Bb + n) * Ee + h * 64 + d;
            *(float2*)dA = make_float2(rna_f(acc[mt][nt][0]), rna_f(acc[mt][nt][1]));
            *(float2*)dB = make_float2(rna_f(acc[mt][nt][2]), rna_f(acc[mt][nt][3]));
        }
    }
}

// ---------------- K6: output projection ----------------
__global__ __launch_bounds__(256, 2) void outproj_mma(
    const float* __restrict__ bo, float* __restrict__ out)
{
    const int n0 = blockIdx.x * 128;
    const int m0 = blockIdx.y * 128;

    const int rl = threadIdx.x >> 3, c4 = threadIdx.x & 7;
    const char* a0 = (const char*)(g_ctx + (size_t)(m0 + rl) * Ee) + c4 * 16;
    const char* b0 = (const char*)(g_wr[3] + (size_t)(n0 + rl) * Ee) + c4 * 16;

    float acc[4][4][4];
    gemm_mma_async(a0, b0, 32L*Ee*4, 32L*Ee*4, 24, 0, false, acc);

    EPI_IDX();
    #pragma unroll
    for (int mt = 0; mt < 4; mt++) {
        const int rA = grow0 + mt * 16, rB = rA + 8;
        #pragma unroll
        for (int nt = 0; nt < 4; nt++) {
            const int cc = gcol0 + nt * 8;
            float2 bb = *(const float2*)(bo + cc);
            *(float2*)(out + (size_t)rA * Ee + cc) =
                make_float2(acc[mt][nt][0] + bb.x, acc[mt][nt][1] + bb.y);
            *(float2*)(out + (size_t)rB * Ee + cc) =
                make_float2(acc[mt][nt][2] + bb.x, acc[mt][nt][3] + bb.y);
        }
    }
}

// ---------------------------------------------------------------------------
extern "C" void kernel_launch(void* const* d_in, const int* in_sizes, int n_in,
                              void* d_out, int out_size)
{
    const float* x         = (const float*)d_in[0];
    const int*   distances = (const int*)  d_in[1];
    const float* Wq = (const float*)d_in[2];
    const float* bq = (const float*)d_in[3];
    const float* Wk = (const float*)d_in[4];
    const float* bk = (const float*)d_in[5];
    const float* Wv = (const float*)d_in[6];
    const float* bv = (const float*)d_in[7];
    const float* Wo = (const float*)d_in[8];
    const float* bo = (const float*)d_in[9];
    const float* rel_bias = (const float*)d_in[10];
    float* out = (float*)d_out;

    cudaFuncSetAttribute(proj_mma,    cudaFuncAttributeMaxDynamicSharedMemorySize, SMEM_DYN);
    cudaFuncSetAttribute(scores_mma,  cudaFuncAttributeMaxDynamicSharedMemorySize, SMEM_DYN);
    cudaFuncSetAttribute(ctx_mma,     cudaFuncAttributeMaxDynamicSharedMemorySize, SMEM_DYN);
    cudaFuncSetAttribute(outproj_mma, cudaFuncAttributeMaxDynamicSharedMemorySize, SMEM_DYN);

    float* d_xr;  cudaGetSymbolAddress((void**)&d_xr, g_xr);
    float* d_wr;  cudaGetSymbolAddress((void**)&d_wr, g_wr);
    float* d_gs;  cudaGetSymbolAddress((void**)&d_gs, g_s);

    round4_kernel<<<(unsigned)((size_t)NTOK*Ee/4/256), 256>>>((const float4*)x, (float4*)d_xr);
    round4_kernel<<<Ee*Ee/4/256, 256>>>((const float4*)Wq, (float4*)(d_wr + 0*(size_t)Ee*Ee));
    round4_kernel<<<Ee*Ee/4/256, 256>>>((const float4*)Wk, (float4*)(d_wr + 1*(size_t)Ee*Ee));
    round4_kernel<<<Ee*Ee/4/256, 256>>>((const float4*)Wv, (float4*)(d_wr + 2*(size_t)Ee*Ee));
    round4_kernel<<<Ee*Ee/4/256, 256>>>((const float4*)Wo, (float4*)(d_wr + 3*(size_t)Ee*Ee));
    bucketize_kernel<<<Hh*Cc*Cc/256, 256>>>(distances);

    proj_mma<<<dim3(6, NTOK/128, 3), 256, SMEM_DYN>>>(bq, bk, bv);
    transpose_v_kernel<<<dim3(8, 32, 144), 256>>>();
    scores_mma<<<dim3(2, 2, 144), 256, SMEM_DYN>>>(rel_bias);

    const size_t out_elems   = (size_t)NTOK * Ee;
    const size_t probs_elems = (size_t)Hh * Bb * Cc * Cc;
    const bool want_probs = ((size_t)out_size >= out_elems + probs_elems);
    // probs written straight into d_out tail (or scratch if not expected)
    softmax_kernel<<<Hh*Bb*Cc, 256>>>(want_probs ? (out + out_elems) : d_gs);

    ctx_mma<<<dim3(8, 2, 144), 256, SMEM_DYN>>>();
    outproj_mma<<<dim3(6, NTOK/128), 256, SMEM_DYN>>>(bo, out);
}

// round 7
// speedup vs baseline: 7.0521x; 1.6936x over previous
#include <cuda_runtime.h>
#include <cuda_fp16.h>
#include <math.h>
#include <stdint.h>

#define Rr   16
#define Cc   256
#define Bb   12
#define Ee   768
#define Hh   12
#define Dd   64
#define RD   1024
#define NTOK 49152
#define SCALING 0.03125f

// fp16 GEMM operands
__device__ __half g_xh [(size_t)NTOK*Ee];
__device__ __half g_wh [4][(size_t)Ee*Ee];
__device__ __half g_qh [(size_t)NTOK*Ee];
__device__ __half g_kh [(size_t)NTOK*Ee];
__device__ __half g_vh [(size_t)NTOK*Ee];
__device__ __half g_vth[(size_t)Hh*Bb*RD*Cc];
__device__ __half g_srh[(size_t)Hh*Bb*Cc*Cc];
__device__ __half g_ctxh[(size_t)NTOK*Ee];
// f32
__device__ float g_s [(size_t)Hh*Bb*Cc*Cc];     // scores (softmax input)
__device__ unsigned char g_buck[(size_t)Hh*Cc*Cc];

#define STAGE_BYTES 32768            // A 16KB + B 16KB (128 rows x 128B each)
#define SMEM_DYN    (3*STAGE_BYTES)  // 3-stage pipeline

// ---------------- helpers ----------------
__device__ __forceinline__ uint32_t smem_u32(const void* p) {
    uint32_t a;
    asm("{ .reg .u64 t; cvta.to.shared.u64 t, %1; cvt.u32.u64 %0, t; }" : "=r"(a) : "l"(p));
    return a;
}
#define CP_ASYNC16(d, s) \
    asm volatile("cp.async.cg.shared.global [%0], [%1], 16;" :: "r"(d), "l"(s) : "memory")
#define CP_COMMIT() asm volatile("cp.async.commit_group;" ::: "memory")
#define CP_WAIT1()  asm volatile("cp.async.wait_group 1;" ::: "memory")
#define LDSM4(r, addr) \
    asm volatile("ldmatrix.sync.aligned.m8n8.x4.shared.b16 {%0,%1,%2,%3}, [%4];" \
        : "=r"((r)[0]), "=r"((r)[1]), "=r"((r)[2]), "=r"((r)[3]) : "r"(addr))
#define MMA_F16(d, a, b) \
    asm volatile("mma.sync.aligned.m16n8k16.row.col.f32.f16.f16.f32 " \
        "{%0,%1,%2,%3}, {%4,%5,%6,%7}, {%8,%9}, {%0,%1,%2,%3};" \
        : "+f"((d)[0]), "+f"((d)[1]), "+f"((d)[2]), "+f"((d)[3]) \
        : "r"((a)[0]), "r"((a)[1]), "r"((a)[2]), "r"((a)[3]), \
          "r"((b)[0]), "r"((b)[1]))

// ---------------- shared GEMM core (fp16) ----------------
// Block 128(M) x 128(N).  K-chunk = 64 halfs = 128B/row.  Both operands
// K-contiguous (NT).  SMEM rows XOR-16B swizzled.  3-stage cp.async.
// Per chunk: 4 k16 steps; per step 4 A-LDSM.x4, 2 B-LDSM.x4, 16 MMA m16n8k16.
__device__ __forceinline__ void gemm_mma_async(
    const char* a0, const char* b0, long arow, long brow,
    int NC, long roff, float acc[4][4][4])
{
    extern __shared__ uint32_t smem[];
    const uint32_t sbase = smem_u32(smem);
    const int t = threadIdx.x;
    const int lane = t & 31, wid = t >> 5;
    const int wm = wid >> 2, wn = wid & 3;

    uint32_t sts[4];
    {
        const int c16 = t & 7;
        #pragma unroll
        for (int i = 0; i < 4; i++) {
            int row = (t >> 3) + 32 * i;
            sts[i] = (uint32_t)(row * 128 + ((c16 ^ (row & 7)) << 4));
        }
    }
    // LDSM offsets relative to stage base (loop-invariant)
    uint32_t arel[4][4];   // [mt][ks]
    uint32_t brel[4][2];   // [ks][p], +16384 folded in
    {
        #pragma unroll
        for (int mt = 0; mt < 4; mt++) {
            int row = wm * 64 + mt * 16 + (lane & 15);
            #pragma unroll
            for (int ks = 0; ks < 4; ks++) {
                int c16 = ks * 2 + (lane >> 4);
                arel[mt][ks] = (uint32_t)(row * 128 + ((c16 ^ (row & 7)) << 4));
            }
        }
        const int mm = lane >> 3;
        #pragma unroll
        for (int p = 0; p < 2; p++) {
            int row = wn * 32 + p * 16 + ((mm >> 1) << 3) + (lane & 7);
            #pragma unroll
            for (int ks = 0; ks < 4; ks++) {
                int c16 = ks * 2 + (mm & 1);
                brel[ks][p] = (uint32_t)(16384 + row * 128 + ((c16 ^ (row & 7)) << 4));
            }
        }
    }
    #pragma unroll
    for (int mt = 0; mt < 4; mt++)
        #pragma unroll
        for (int nt = 0; nt < 4; nt++)
            #pragma unroll
            for (int r = 0; r < 4; r++) acc[mt][nt][r] = 0.0f;

    // prologue: stages 0,1
    #pragma unroll
    for (int s = 0; s < 2; s++) {
        const long o = (long)s * roff;
        const uint32_t d = sbase + (uint32_t)s * STAGE_BYTES;
        #pragma unroll
        for (int i = 0; i < 4; i++) {
            CP_ASYNC16(d + sts[i],          a0 + i * arow + o);
            CP_ASYNC16(d + 16384u + sts[i], b0 + i * brow + o);
        }
        CP_COMMIT();
    }

    int sc = 0;
    for (int c = 0; c < NC; c++) {
        CP_WAIT1();
        __syncthreads();
        if (c + 2 < NC) {
            const long o = (long)(c + 2) * roff;
            int sn = sc + 2; if (sn >= 3) sn -= 3;
            const uint32_t d = sbase + (uint32_t)sn * STAGE_BYTES;
            #pragma unroll
            for (int i = 0; i < 4; i++) {
                CP_ASYNC16(d + sts[i],          a0 + i * arow + o);
                CP_ASYNC16(d + 16384u + sts[i], b0 + i * brow + o);
            }
            CP_COMMIT();
        } else {
            CP_COMMIT();
        }

        const uint32_t sa = sbase + (uint32_t)sc * STAGE_BYTES;
        #pragma unroll
        for (int ks = 0; ks < 4; ks++) {
            uint32_t af[4][4], bf[4][2];
            #pragma unroll
            for (int mt = 0; mt < 4; mt++) LDSM4(af[mt], sa + arel[mt][ks]);
            #pragma unroll
            for (int p = 0; p < 2; p++) {
                uint32_t r4[4];
                LDSM4(r4, sa + brel[ks][p]);
                bf[2*p+0][0] = r4[0]; bf[2*p+0][1] = r4[1];
                bf[2*p+1][0] = r4[2]; bf[2*p+1][1] = r4[3];
            }
            #pragma unroll
            for (int mt = 0; mt < 4; mt++)
                #pragma unroll
                for (int nt = 0; nt < 4; nt++)
                    MMA_F16(acc[mt][nt], af[mt], bf[nt]);
        }
        if (++sc == 3) sc = 0;
    }
}

#define EPI_IDX()                                                         \
    const int lane = threadIdx.x & 31, wid = threadIdx.x >> 5;            \
    const int wm = wid >> 2, wn = wid & 3;                                \
    const int grow0 = m0 + wm * 64 + (lane >> 2);                         \
    const int gcol0 = n0 + wn * 32 + (lane & 3) * 2;

// ---------------- small kernels ----------------
__device__ __forceinline__ int rel_bucket(int dist) {
    if (dist < 16) return dist;
    float v = logf(fmaxf((float)dist, 1.0f) * 0.0625f) * (15.0f / 8.047189562170502f);
    int b = 16 + (int)v;
    return b < 31 ? b : 31;
}
__global__ __launch_bounds__(256) void bucketize_kernel(const int* __restrict__ dist) {
    size_t i = (size_t)blockIdx.x * 256 + threadIdx.x;
    g_buck[i] = (unsigned char)rel_bucket(__ldg(&dist[i]));
}
struct h4 { __half2 a, b; };
__global__ __launch_bounds__(256) void pack_h_kernel(const float4* __restrict__ src,
                                                     h4* __restrict__ dst) {
    size_t i = (size_t)blockIdx.x * 256 + threadIdx.x;
    float4 v = __ldg(&src[i]);
    h4 o;
    o.a = __floats2half2_rn(v.x, v.y);
    o.b = __floats2half2_rn(v.z, v.w);
    dst[i] = o;
}

// ---------------- K1: QKV projection ----------------
__global__ __launch_bounds__(256, 2) void proj_mma(
    const float* __restrict__ bq, const float* __restrict__ bk, const float* __restrict__ bv)
{
    const int w  = blockIdx.z;
    const int n0 = blockIdx.x * 128;
    const int m0 = blockIdx.y * 128;
    const float* bias = (w == 0) ? bq : (w == 1) ? bk : bv;
    __half*      dst  = (w == 0) ? g_qh : (w == 1) ? g_kh : g_vh;
    const float  scale = (w == 0) ? SCALING : 1.0f;

    const int rl = threadIdx.x >> 3, c4 = threadIdx.x & 7;
    const char* a0 = (const char*)(g_xh + (size_t)(m0 + rl) * Ee) + c4 * 16;
    const char* b0 = (const char*)(g_wh[w] + (size_t)(n0 + rl) * Ee) + c4 * 16;

    float acc[4][4][4];
    gemm_mma_async(a0, b0, 32L*Ee*2, 32L*Ee*2, 12, 128, acc);

    EPI_IDX();
    #pragma unroll
    for (int mt = 0; mt < 4; mt++) {
        const int rA = grow0 + mt * 16, rB = rA + 8;
        #pragma unroll
        for (int nt = 0; nt < 4; nt++) {
            const int cc = gcol0 + nt * 8;
            float2 bb = *(const float2*)(bias + cc);
            *(__half2*)(dst + (size_t)rA * Ee + cc) = __floats2half2_rn(
                (acc[mt][nt][0] + bb.x) * scale, (acc[mt][nt][1] + bb.y) * scale);
            *(__half2*)(dst + (size_t)rB * Ee + cc) = __floats2half2_rn(
                (acc[mt][nt][2] + bb.x) * scale, (acc[mt][nt][3] + bb.y) * scale);
        }
    }
}

// ---------------- K2: V transpose -> g_vth[hn][rd][j] ----------------
__global__ __launch_bounds__(256) void transpose_v_kernel()
{
    __shared__ __half tile[32][40];
    const int t = threadIdx.x;
    const int tx = t & 31, a0 = t >> 5;
    const int jb = blockIdx.x, rdb = blockIdx.y, hn = blockIdx.z;
    const int h = hn / 12, n = hn % 12;
    const int r = rdb >> 1, d0 = (rdb & 1) * 32;
    #pragma unroll
    for (int i = 0; i < 4; i++) {
        int jl = a0 + 8 * i;
        int j = jb * 32 + jl;
        tile[jl][tx] = g_vh[((size_t)(r * Cc + j) * Bb + n) * Ee + h * 64 + d0 + tx];
    }
    __syncthreads();
    #pragma unroll
    for (int i = 0; i < 4; i++) {
        int dl = a0 + 8 * i;
        g_vth[((size_t)hn * RD + rdb * 32 + dl) * Cc + jb * 32 + tx] = tile[tx][dl];
    }
}

// ---------------- K3: scores + bucket bias ----------------
__global__ __launch_bounds__(256, 2) void scores_mma(const float* __restrict__ rel_bias)
{
    const int n0 = blockIdx.x * 128;
    const int m0 = blockIdx.y * 128;
    const int hn = blockIdx.z;
    const int h = hn / 12, n = hn % 12;

    const int rl = threadIdx.x >> 3, c4 = threadIdx.x & 7;
    const char* a0 = (const char*)(g_qh + ((size_t)(m0 + rl) * Bb + n) * Ee + h * 64) + c4 * 16;
    const char* b0 = (const char*)(g_kh + ((size_t)(n0 + rl) * Bb + n) * Ee + h * 64) + c4 * 16;

    float acc[4][4][4];
    // one chunk per r (K=64 halfs); advance r via roff
    gemm_mma_async(a0, b0, 32L*Bb*Ee*2, 32L*Bb*Ee*2, 16, (long)Cc*Bb*Ee*2, acc);

    EPI_IDX();
    #pragma unroll
    for (int mt = 0; mt < 4; mt++) {
        const int iA = grow0 + mt * 16, iB = iA + 8;
        const unsigned char* bA = g_buck + ((size_t)h * Cc + iA) * Cc;
        const unsigned char* bB = g_buck + ((size_t)h * Cc + iB) * Cc;
        float* sA = g_s + ((size_t)hn * Cc + iA) * Cc;
        float* sB = g_s + ((size_t)hn * Cc + iB) * Cc;
        #pragma unroll
        for (int nt = 0; nt < 4; nt++) {
            const int cc = gcol0 + nt * 8;
            *(float2*)(sA + cc) = make_float2(
                acc[mt][nt][0] + __ldg(&rel_bias[bA[cc]   * Hh + n]),
                acc[mt][nt][1] + __ldg(&rel_bias[bA[cc+1] * Hh + n]));
            *(float2*)(sB + cc) = make_float2(
                acc[mt][nt][2] + __ldg(&rel_bias[bB[cc]   * Hh + n]),
                acc[mt][nt][3] + __ldg(&rel_bias[bB[cc+1] * Hh + n]));
        }
    }
}

// ---------------- K4: softmax; probs -> dst (d_out tail) + fp16 copy ----
__global__ __launch_bounds__(256) void softmax_kernel(float* __restrict__ dst)
{
    const float* p = g_s + (size_t)blockIdx.x * Cc;
    float*  pd = dst   + (size_t)blockIdx.x * Cc;
    __half* pr = g_srh + (size_t)blockIdx.x * Cc;
    const int t = threadIdx.x, lane = t & 31, w = t >> 5;
    __shared__ float red[8];
    float v = p[t];
    float m = v;
    #pragma unroll
    for (int o = 16; o > 0; o >>= 1) m = fmaxf(m, __shfl_xor_sync(~0u, m, o));
    if (lane == 0) red[w] = m;
    __syncthreads();
    if (w == 0) {
        float mm = red[lane & 7];
        #pragma unroll
        for (int o = 4; o > 0; o >>= 1) mm = fmaxf(mm, __shfl_xor_sync(~0u, mm, o));
        if (lane == 0) red[0] = mm;
    }
    __syncthreads();
    m = red[0];
    __syncthreads();
    float e = expf(v - m), s = e;
    #pragma unroll
    for (int o = 16; o > 0; o >>= 1) s += __shfl_xor_sync(~0u, s, o);
    if (lane == 0) red[w] = s;
    __syncthreads();
    if (w == 0) {
        float ss = red[lane & 7];
        #pragma unroll
        for (int o = 4; o > 0; o >>= 1) ss += __shfl_xor_sync(~0u, ss, o);
        if (lane == 0) red[0] = ss;
    }
    __syncthreads();
    float prob = e / red[0];
    pd[t] = prob;
    pr[t] = __float2half_rn(prob);
}

// ---------------- K5: context = P @ Vt -> token layout fp16 --------
__global__ __launch_bounds__(256, 2) void ctx_mma()
{
    const int n0 = blockIdx.x * 128;   // rd
    const int m0 = blockIdx.y * 128;   // i
    const int hn = blockIdx.z;
    const int h = hn / 12, n = hn % 12;

    const int rl = threadIdx.x >> 3, c4 = threadIdx.x & 7;
    const char* a0 = (const char*)(g_srh + ((size_t)hn * Cc + m0 + rl) * Cc) + c4 * 16;
    const char* b0 = (const char*)(g_vth + ((size_t)hn * RD + n0 + rl) * Cc) + c4 * 16;

    float acc[4][4][4];
    gemm_mma_async(a0, b0, 32L*Cc*2, 32L*Cc*2, 4, 128, acc);

    EPI_IDX();
    #pragma unroll
    for (int mt = 0; mt < 4; mt++) {
        const int iA = grow0 + mt * 16, iB = iA + 8;
        #pragma unroll
        for (int nt = 0; nt < 4; nt++) {
            const int cc = gcol0 + nt * 8;
            const int r = cc >> 6, d = cc & 63;
            __half* dA = g_ctxh + (((size_t)(r * Cc + iA)) * Bb + n) * Ee + h * 64 + d;
            __half* dB = g_ctxh + (((size_t)(r * Cc + iB)) * Bb + n) * Ee + h * 64 + d;
            *(__half2*)dA = __floats2half2_rn(acc[mt][nt][0], acc[mt][nt][1]);
            *(__half2*)dB = __floats2half2_rn(acc[mt][nt][2], acc[mt][nt][3]);
        }
    }
}

// ---------------- K6: output projection (f32 out) ----------------
__global__ __launch_bounds__(256, 2) void outproj_mma(
    const float* __restrict__ bo, float* __restrict__ out)
{
    const int n0 = blockIdx.x * 128;
    const int m0 = blockIdx.y * 128;

    const int rl = threadIdx.x >> 3, c4 = threadIdx.x & 7;
    const char* a0 = (const char*)(g_ctxh + (size_t)(m0 + rl) * Ee) + c4 * 16;
    const char* b0 = (const char*)(g_wh[3] + (size_t)(n0 + rl) * Ee) + c4 * 16;

    float acc[4][4][4];
    gemm_mma_async(a0, b0, 32L*Ee*2, 32L*Ee*2, 12, 128, acc);

    EPI_IDX();
    #pragma unroll
    for (int mt = 0; mt < 4; mt++) {
        const int rA = grow0 + mt * 16, rB = rA + 8;
        #pragma unroll
        for (int nt = 0; nt < 4; nt++) {
            const int cc = gcol0 + nt * 8;
            float2 bb = *(const float2*)(bo + cc);
            *(float2*)(out + (size_t)rA * Ee + cc) =
                make_float2(acc[mt][nt][0] + bb.x, acc[mt][nt][1] + bb.y);
            *(float2*)(out + (size_t)rB * Ee + cc) =
                make_float2(acc[mt][nt][2] + bb.x, acc[mt][nt][3] + bb.y);
        }
    }
}

// ---------------------------------------------------------------------------
extern "C" void kernel_launch(void* const* d_in, const int* in_sizes, int n_in,
                              void* d_out, int out_size)
{
    const float* x         = (const float*)d_in[0];
    const int*   distances = (const int*)  d_in[1];
    const float* Wq = (const float*)d_in[2];
    const float* bq = (const float*)d_in[3];
    const float* Wk = (const float*)d_in[4];
    const float* bk = (const float*)d_in[5];
    const float* Wv = (const float*)d_in[6];
    const float* bv = (const float*)d_in[7];
    const float* Wo = (const float*)d_in[8];
    const float* bo = (const float*)d_in[9];
    const float* rel_bias = (const float*)d_in[10];
    float* out = (float*)d_out;

    cudaFuncSetAttribute(proj_mma,    cudaFuncAttributeMaxDynamicSharedMemorySize, SMEM_DYN);
    cudaFuncSetAttribute(scores_mma,  cudaFuncAttributeMaxDynamicSharedMemorySize, SMEM_DYN);
    cudaFuncSetAttribute(ctx_mma,     cudaFuncAttributeMaxDynamicSharedMemorySize, SMEM_DYN);
    cudaFuncSetAttribute(outproj_mma, cudaFuncAttributeMaxDynamicSharedMemorySize, SMEM_DYN);

    __half* d_xh;  cudaGetSymbolAddress((void**)&d_xh, g_xh);
    __half* d_wh;  cudaGetSymbolAddress((void**)&d_wh, g_wh);
    float*  d_gs;  cudaGetSymbolAddress((void**)&d_gs, g_s);

    pack_h_kernel<<<(unsigned)((size_t)NTOK*Ee/4/256), 256>>>((const float4*)x, (h4*)d_xh);
    pack_h_kernel<<<Ee*Ee/4/256, 256>>>((const float4*)Wq, (h4*)(d_wh + 0*(size_t)Ee*Ee));
    pack_h_kernel<<<Ee*Ee/4/256, 256>>>((const float4*)Wk, (h4*)(d_wh + 1*(size_t)Ee*Ee));
    pack_h_kernel<<<Ee*Ee/4/256, 256>>>((const float4*)Wv, (h4*)(d_wh + 2*(size_t)Ee*Ee));
    pack_h_kernel<<<Ee*Ee/4/256, 256>>>((const float4*)Wo, (h4*)(d_wh + 3*(size_t)Ee*Ee));
    bucketize_kernel<<<Hh*Cc*Cc/256, 256>>>(distances);

    proj_mma<<<dim3(6, NTOK/128, 3), 256, SMEM_DYN>>>(bq, bk, bv);
    transpose_v_kernel<<<dim3(8, 32, 144), 256>>>();
    scores_mma<<<dim3(2, 2, 144), 256, SMEM_DYN>>>(rel_bias);

    const size_t out_elems   = (size_t)NTOK * Ee;
    const size_t probs_elems = (size_t)Hh * Bb * Cc * Cc;
    const bool want_probs = ((size_t)out_size >= out_elems + probs_elems);
    softmax_kernel<<<Hh*Bb*Cc, 256>>>(want_probs ? (out + out_elems) : d_gs);

    ctx_mma<<<dim3(8, 2, 144), 256, SMEM_DYN>>>();
    outproj_mma<<<dim3(6, NTOK/128), 256, SMEM_DYN>>>(bo, out);
}